// round 14
// baseline (speedup 1.0000x reference)
#include <cuda_runtime.h>
#include <cuda_fp16.h>
#include <stdint.h>

// Problem constants
#define Bc   4
#define Tc   1024
#define Lc   1024
#define Dc   1024
#define Hc   16
#define HSc  64
#define ROTc 32

// ---------------- scratch (device globals; no allocation allowed) ----------
__device__ __half g_pa[Bc * Tc * Dc];
__device__ __half g_q16[Bc * Tc * Dc];
__device__ __half g_k16[Bc * Lc * Dc];
__device__ __half g_y16[Bc * Tc * Dc];
__device__ __half g_vT[Bc * Hc * HSc * Lc];
__device__ __half g_w16q[Dc * Dc];
__device__ __half g_w16k[Dc * Dc];
__device__ __half g_w16v[Dc * Dc];
__device__ __half g_w16o[Dc * Dc];

__device__ __forceinline__ uint32_t smem_u32(const void* p) {
    uint32_t a;
    asm("{ .reg .u64 t; cvta.to.shared.u64 t, %1; cvt.u32.u64 %0, t; }" : "=r"(a) : "l"(p));
    return a;
}

#define MMA_F16(acc, a0, a1, a2, a3, b0, b1)                                      \
    asm volatile(                                                                 \
        "mma.sync.aligned.m16n8k16.row.col.f32.f16.f16.f32 "                      \
        "{%0,%1,%2,%3},{%4,%5,%6,%7},{%8,%9},{%0,%1,%2,%3};"                      \
        : "+f"(acc[0]), "+f"(acc[1]), "+f"(acc[2]), "+f"(acc[3])                  \
        : "r"(a0), "r"(a1), "r"(a2), "r"(a3), "r"(b0), "r"(b1))

#define LDSM4(r0, r1, r2, r3, addr)                                               \
    asm volatile("ldmatrix.sync.aligned.m8n8.x4.shared.b16 {%0,%1,%2,%3}, [%4];"  \
        : "=r"(r0), "=r"(r1), "=r"(r2), "=r"(r3) : "r"(addr))

#define CP16(dst, src)                                                            \
    asm volatile("cp.async.cg.shared.global [%0], [%1], 16;" :: "r"(dst), "l"(src))
#define CP_COMMIT() asm volatile("cp.async.commit_group;" ::: "memory")
#define CP_WAIT0()  asm volatile("cp.async.wait_group 0;" ::: "memory")

__device__ __forceinline__ float ex2f(float x) {
    float r;
    asm("ex2.approx.f32 %0, %1;" : "=f"(r) : "f"(x));
    return r;
}

// ---------------------------------------------------------------------------
// pack: fp32 [rows x 1024] -> fp16
// ---------------------------------------------------------------------------
__global__ void pack16_kernel(const float* __restrict__ src, __half* __restrict__ dst) {
    int m = blockIdx.x;
    int c = threadIdx.x * 4;
    float4 v = *(const float4*)(src + (size_t)m * Dc + c);
    __half2* d = (__half2*)(dst + (size_t)m * Dc + c);
    d[0] = __floats2half2_rn(v.x, v.y);
    d[1] = __floats2half2_rn(v.z, v.w);
}

__global__ void pack16x4_kernel(const float* __restrict__ s0, __half* __restrict__ d0,
                                const float* __restrict__ s1, __half* __restrict__ d1,
                                const float* __restrict__ s2, __half* __restrict__ d2,
                                const float* __restrict__ s3, __half* __restrict__ d3) {
    const float* src; __half* dst;
    switch (blockIdx.y) {
        case 0: src = s0; dst = d0; break;
        case 1: src = s1; dst = d1; break;
        case 2: src = s2; dst = d2; break;
        default: src = s3; dst = d3; break;
    }
    int m = blockIdx.x;
    int c = threadIdx.x * 4;
    float4 v = *(const float4*)(src + (size_t)m * Dc + c);
    __half2* d = (__half2*)(dst + (size_t)m * Dc + c);
    d[0] = __floats2half2_rn(v.x, v.y);
    d[1] = __floats2half2_rn(v.z, v.w);
}

// ---------------------------------------------------------------------------
// Multi-output dense GEMM fp16, 64-wide k-tiles, TWO-stage pipeline so 3 CTAs
// fit per SM (73.7 KB smem; occ 16 -> 24 warps/SM). Fused epilogues.
// MODE 0: QKV stage1 (sel0 q+rope, sel1 k+rope, sel2 v->vT transposed)
// MODE 1: single GEMM fp16 out | MODE 2: KV stage2 | MODE 3: fp32 out
// ---------------------------------------------------------------------------
#define STG_SZ 36864
#define SMEM_TC (2 * STG_SZ)

template <int MODE>
__global__ __launch_bounds__(256, 3) void gemm16_multi(
        const __half* __restrict__ Ap,
        const __half* __restrict__ W0, const __half* __restrict__ W1,
        const __half* __restrict__ W2,
        const float* __restrict__ b0, const float* __restrict__ b1,
        const float* __restrict__ b2,
        void* __restrict__ C0, void* __restrict__ C1, void* __restrict__ C2,
        const float* __restrict__ R) {
    extern __shared__ char smem[];
    const uint32_t sb = smem_u32(smem);

    int sel = 0;
    if (MODE == 0 || MODE == 2) sel = blockIdx.x >> 3;

    const __half* Wp = (sel == 0) ? W0 : (sel == 1 ? W1 : W2);
    const float*  bp = (sel == 0) ? b0 : (sel == 1 ? b1 : b2);
    void*         Cp = (sel == 0) ? C0 : (sel == 1 ? C1 : C2);

    const int n00 = (blockIdx.x & 7) * 128;

    const int tid = threadIdx.x;
    const int lane = tid & 31;
    const int warp = tid >> 5;
    const int g = lane >> 2, tig = lane & 3;
    const int wm = warp >> 2, wn = warp & 3;

    const bool do_rope = (MODE == 0) && (sel < 2) && ((wn & 1) == 0);
    const bool do_vt   = (MODE == 0 && sel == 2) || (MODE == 2 && sel == 1);

    const __half* Arow = Ap + (size_t)(blockIdx.y * 128) * Dc;
    const __half* Brow = Wp + (size_t)n00 * Dc;

    float acc[4][4][4] = {};

#define LOAD_TILE(kt, stage) do {                                                 \
        uint32_t base_ = sb + (stage) * STG_SZ;                                   \
        _Pragma("unroll")                                                         \
        for (int i_ = 0; i_ < 4; ++i_) {                                          \
            int idx_ = tid + i_ * 256;                                            \
            int row_ = idx_ >> 3, cc_ = idx_ & 7;                                 \
            CP16(base_ + row_ * 144 + cc_ * 16,                                   \
                 Arow + (size_t)row_ * Dc + (kt) * 64 + cc_ * 8);                 \
            CP16(base_ + 18432 + row_ * 144 + cc_ * 16,                           \
                 Brow + (size_t)row_ * Dc + (kt) * 64 + cc_ * 8);                 \
        }                                                                         \
        CP_COMMIT();                                                              \
    } while (0)

    LOAD_TILE(0, 0);

    const int NT = 16;
    for (int kt = 0; kt < NT; ++kt) {
        CP_WAIT0();
        __syncthreads();
        if (kt + 1 < NT) LOAD_TILE(kt + 1, (kt + 1) & 1);

        const uint32_t Ab = sb + (kt & 1) * STG_SZ;
        const uint32_t Bb = Ab + 18432;
        const int arow = lane & 15;
        const int acol = (lane >> 4) * 16;
#pragma unroll
        for (int ks = 0; ks < 4; ++ks) {
            uint32_t a[4][4], bt[2][4];
#pragma unroll
            for (int mi = 0; mi < 4; ++mi) {
                uint32_t ad = Ab + (wm * 64 + mi * 16 + arow) * 144 + ks * 32 + acol;
                LDSM4(a[mi][0], a[mi][1], a[mi][2], a[mi][3], ad);
            }
#pragma unroll
            for (int nb = 0; nb < 2; ++nb) {
                uint32_t bd = Bb + (wn * 32 + nb * 16 + arow) * 144 + ks * 32 + acol;
                LDSM4(bt[nb][0], bt[nb][1], bt[nb][2], bt[nb][3], bd);
            }
#pragma unroll
            for (int mi = 0; mi < 4; ++mi)
#pragma unroll
                for (int ni = 0; ni < 4; ++ni)
                    MMA_F16(acc[mi][ni], a[mi][0], a[mi][1], a[mi][2], a[mi][3],
                            bt[ni >> 1][ni & 1], bt[ni >> 1][(ni & 1) + 2]);
        }
        __syncthreads();
    }
#undef LOAD_TILE

#pragma unroll
    for (int mi = 0; mi < 4; ++mi) {
#pragma unroll
        for (int ni = 0; ni < 4; ++ni) {
            int n = n00 + wn * 32 + ni * 8 + 2 * tig;
            float2 bv = *(const float2*)(bp + n);
            acc[mi][ni][0] += bv.x; acc[mi][ni][1] += bv.y;
            acc[mi][ni][2] += bv.x; acc[mi][ni][3] += bv.y;
        }
    }

    if (do_rope) {
#pragma unroll
        for (int mi = 0; mi < 4; ++mi) {
            int m = blockIdx.y * 128 + wm * 64 + mi * 16 + g;
            int t = m & 1023;
#pragma unroll
            for (int ni = 0; ni < 2; ++ni) {
                int p = ni * 8 + 2 * tig;
                float2 cA = *(const float2*)(R + t * ROTc + p);
                float2 sA = *(const float2*)(R + Tc * ROTc + t * ROTc + p);
                float2 cB = *(const float2*)(R + (t + 8) * ROTc + p);
                float2 sB = *(const float2*)(R + Tc * ROTc + (t + 8) * ROTc + p);
                float a0 = acc[mi][ni][0], a1 = acc[mi][ni][1];
                float a2 = acc[mi][ni][2], a3 = acc[mi][ni][3];
                float q0 = acc[mi][ni + 2][0], q1 = acc[mi][ni + 2][1];
                float q2 = acc[mi][ni + 2][2], q3 = acc[mi][ni + 2][3];
                acc[mi][ni][0]     = a0 * cA.x - q0 * sA.x;
                acc[mi][ni + 2][0] = q0 * cA.x + a0 * sA.x;
                acc[mi][ni][1]     = a1 * cA.y - q1 * sA.y;
                acc[mi][ni + 2][1] = q1 * cA.y + a1 * sA.y;
                acc[mi][ni][2]     = a2 * cB.x - q2 * sB.x;
                acc[mi][ni + 2][2] = q2 * cB.x + a2 * sB.x;
                acc[mi][ni][3]     = a3 * cB.y - q3 * sB.y;
                acc[mi][ni + 2][3] = q3 * cB.y + a3 * sB.y;
            }
        }
    }

    if (do_vt) {
        __half* VT = (__half*)Cp;
#pragma unroll
        for (int mi = 0; mi < 4; ++mi) {
            int m = blockIdx.y * 128 + wm * 64 + mi * 16 + g;
            int bb = m >> 10, l = m & 1023;
#pragma unroll
            for (int ni = 0; ni < 4; ++ni) {
                int n = n00 + wn * 32 + ni * 8 + 2 * tig;
                int h = n >> 6, j = n & 63;
                __half* base = VT + ((size_t)((bb * 16 + h) * 64 + j)) * Lc;
                base[l]            = __float2half_rn(acc[mi][ni][0]);
                base[Lc + l]       = __float2half_rn(acc[mi][ni][1]);
                base[l + 8]        = __float2half_rn(acc[mi][ni][2]);
                base[Lc + l + 8]   = __float2half_rn(acc[mi][ni][3]);
            }
        }
    } else if (MODE == 3) {
        float* C = (float*)Cp;
#pragma unroll
        for (int mi = 0; mi < 4; ++mi) {
            int m = blockIdx.y * 128 + wm * 64 + mi * 16 + g;
#pragma unroll
            for (int ni = 0; ni < 4; ++ni) {
                int n = n00 + wn * 32 + ni * 8 + 2 * tig;
                *(float2*)(C + (size_t)m * Dc + n) =
                    make_float2(acc[mi][ni][0], acc[mi][ni][1]);
                *(float2*)(C + (size_t)(m + 8) * Dc + n) =
                    make_float2(acc[mi][ni][2], acc[mi][ni][3]);
            }
        }
    } else {
        __half* C = (__half*)Cp;
#pragma unroll
        for (int mi = 0; mi < 4; ++mi) {
            int m = blockIdx.y * 128 + wm * 64 + mi * 16 + g;
#pragma unroll
            for (int ni = 0; ni < 4; ++ni) {
                int n = n00 + wn * 32 + ni * 8 + 2 * tig;
                *(__half2*)(C + (size_t)m * Dc + n) =
                    __floats2half2_rn(acc[mi][ni][0], acc[mi][ni][1]);
                *(__half2*)(C + (size_t)(m + 8) * Dc + n) =
                    __floats2half2_rn(acc[mi][ni][2], acc[mi][ni][3]);
            }
        }
    }
}

// ---------------------------------------------------------------------------
// Flash attention (round-11 best): CTA = 256 q-rows, 8 warps x 32 rows
// (2 groups of 16); each K/V ldmatrix feeds 4 MMAs.
// smem: Q 256x144 | 2 stages x (K 128x144 + V 64x272).
// ---------------------------------------------------------------------------
#define FL_Q    0
#define FL_KV   36864
#define FL_STG  35840           // K 18432 + V 17408
#define SMEM_FL (36864 + 2 * FL_STG)

__global__ __launch_bounds__(256, 1) void flash_kernel(
        const __half* __restrict__ Q, const __half* __restrict__ K,
        const __half* __restrict__ VT, __half* __restrict__ Y) {
    extern __shared__ char smem[];
    const uint32_t sb = smem_u32(smem);

    const int z = blockIdx.y;
    const int b = z >> 4, h = z & 15;
    const int t0 = blockIdx.x * 256;
    const int tid = threadIdx.x;
    const int lane = tid & 31;
    const int warp = tid >> 5;
    const int g = lane >> 2, tig = lane & 3;
    const int arow = lane & 15;
    const int acol = (lane >> 4) * 16;

    const __half* Qbase = Q  + ((size_t)b * Tc + t0) * Dc + h * HSc;
    const __half* Kbase = K  + (size_t)b * Lc * Dc + h * HSc;
    const __half* Vbase = VT + (size_t)z * HSc * Lc;

    {   // Q tile: 256 rows x 128B (8 CP16 per thread)
#pragma unroll
        for (int i = 0; i < 8; ++i) {
            int idx = tid + i * 256;
            int row = idx >> 3, cc = idx & 7;
            CP16(sb + FL_Q + row * 144 + cc * 16,
                 Qbase + (size_t)row * Dc + cc * 8);
        }
        CP_COMMIT();
    }

#define LOADC(c, st) do {                                                         \
        uint32_t kb_ = sb + FL_KV + (st) * FL_STG;                                \
        uint32_t vb_ = kb_ + 18432;                                               \
        _Pragma("unroll")                                                         \
        for (int i_ = 0; i_ < 4; ++i_) {                                          \
            int idx_ = tid + i_ * 256;                                            \
            int krow_ = idx_ >> 3, kcc_ = idx_ & 7;                               \
            CP16(kb_ + krow_ * 144 + kcc_ * 16,                                   \
                 Kbase + (size_t)((c) * 128 + krow_) * Dc + kcc_ * 8);            \
            int vrow_ = idx_ >> 4, vcc_ = idx_ & 15;                              \
            CP16(vb_ + vrow_ * 272 + vcc_ * 16,                                   \
                 Vbase + (size_t)vrow_ * Lc + (c) * 128 + vcc_ * 8);              \
        }                                                                         \
        CP_COMMIT();                                                              \
    } while (0)

    LOADC(0, 0);
    CP_WAIT0();
    __syncthreads();

    // Q fragments for both 16-row groups; fold 0.125*log2(e)
    uint32_t qa[2][4][4];
#pragma unroll
    for (int G = 0; G < 2; ++G)
#pragma unroll
        for (int kb = 0; kb < 4; ++kb) {
            uint32_t ad = sb + FL_Q + (warp * 32 + G * 16 + arow) * 144 + kb * 32 + acol;
            LDSM4(qa[G][kb][0], qa[G][kb][1], qa[G][kb][2], qa[G][kb][3], ad);
        }
    {
        const __half2 sc = __floats2half2_rn(0.1803368801f, 0.1803368801f);
        const uint32_t scu = *(const uint32_t*)&sc;
#pragma unroll
        for (int G = 0; G < 2; ++G)
#pragma unroll
            for (int kb = 0; kb < 4; ++kb)
#pragma unroll
                for (int r = 0; r < 4; ++r) {
                    __half2 t = __hmul2(*(__half2*)&qa[G][kb][r], *(__half2*)&scu);
                    qa[G][kb][r] = *(uint32_t*)&t;
                }
    }

    float lsum[2][2] = {};
    float acc[2][8][4] = {};

    for (int c = 0; c < 8; ++c) {
        if (c > 0) { CP_WAIT0(); __syncthreads(); }
        if (c + 1 < 8) LOADC(c + 1, (c + 1) & 1);

        const uint32_t Kb = sb + FL_KV + (c & 1) * FL_STG;
        const uint32_t Vb = Kb + 18432;

#pragma unroll
        for (int hh = 0; hh < 2; ++hh) {
            float s[2][8][4] = {};
#pragma unroll
            for (int kb = 0; kb < 4; ++kb) {
#pragma unroll
                for (int nb2 = 0; nb2 < 4; ++nb2) {
                    uint32_t b0, b1, b2, b3;
                    LDSM4(b0, b1, b2, b3,
                          Kb + (hh * 64 + nb2 * 16 + arow) * 144 + kb * 32 + acol);
#pragma unroll
                    for (int G = 0; G < 2; ++G) {
                        MMA_F16(s[G][nb2 * 2],     qa[G][kb][0], qa[G][kb][1],
                                qa[G][kb][2], qa[G][kb][3], b0, b2);
                        MMA_F16(s[G][nb2 * 2 + 1], qa[G][kb][0], qa[G][kb][1],
                                qa[G][kb][2], qa[G][kb][3], b1, b3);
                    }
                }
            }
            uint32_t pa_[2][4][4];
#pragma unroll
            for (int G = 0; G < 2; ++G)
#pragma unroll
                for (int nb = 0; nb < 8; ++nb) {
                    float e0 = ex2f(s[G][nb][0]);
                    float e1 = ex2f(s[G][nb][1]);
                    float e2 = ex2f(s[G][nb][2]);
                    float e3 = ex2f(s[G][nb][3]);
                    lsum[G][0] += e0 + e1; lsum[G][1] += e2 + e3;
                    __half2 p01 = __floats2half2_rn(e0, e1);
                    __half2 p23 = __floats2half2_rn(e2, e3);
                    int kb2 = nb >> 1;
                    if ((nb & 1) == 0) {
                        pa_[G][kb2][0] = *(uint32_t*)&p01;
                        pa_[G][kb2][1] = *(uint32_t*)&p23;
                    } else {
                        pa_[G][kb2][2] = *(uint32_t*)&p01;
                        pa_[G][kb2][3] = *(uint32_t*)&p23;
                    }
                }
#pragma unroll
            for (int kb2 = 0; kb2 < 4; ++kb2) {
#pragma unroll
                for (int jb2 = 0; jb2 < 4; ++jb2) {
                    uint32_t v0, v1, v2, v3;
                    LDSM4(v0, v1, v2, v3,
                          Vb + (jb2 * 16 + arow) * 272 + hh * 128 + kb2 * 32 + acol);
#pragma unroll
                    for (int G = 0; G < 2; ++G) {
                        MMA_F16(acc[G][jb2 * 2],     pa_[G][kb2][0], pa_[G][kb2][1],
                                pa_[G][kb2][2], pa_[G][kb2][3], v0, v2);
                        MMA_F16(acc[G][jb2 * 2 + 1], pa_[G][kb2][0], pa_[G][kb2][1],
                                pa_[G][kb2][2], pa_[G][kb2][3], v1, v3);
                    }
                }
            }
        }
    }
#undef LOADC

#pragma unroll
    for (int G = 0; G < 2; ++G) {
        float l0 = lsum[G][0], l1 = lsum[G][1];
        l0 += __shfl_xor_sync(0xffffffffu, l0, 1);
        l0 += __shfl_xor_sync(0xffffffffu, l0, 2);
        l1 += __shfl_xor_sync(0xffffffffu, l1, 1);
        l1 += __shfl_xor_sync(0xffffffffu, l1, 2);
        const float inv0 = __frcp_rn(l0), inv1 = __frcp_rn(l1);
        __half* Yy = Y + ((size_t)b * Tc + t0 + warp * 32 + G * 16) * Dc + h * HSc;
#pragma unroll
        for (int jnb = 0; jnb < 8; ++jnb) {
            int col = jnb * 8 + 2 * tig;
            *(__half2*)(Yy + (size_t)g * Dc + col) =
                __floats2half2_rn(acc[G][jnb][0] * inv0, acc[G][jnb][1] * inv0);
            *(__half2*)(Yy + (size_t)(g + 8) * Dc + col) =
                __floats2half2_rn(acc[G][jnb][2] * inv1, acc[G][jnb][3] * inv1);
        }
    }
}

// ---------------------------------------------------------------------------
extern "C" void kernel_launch(void* const* d_in, const int* in_sizes, int n_in,
                              void* d_out, int out_size) {
    const float* x   = (const float*)d_in[0];
    const float* mem = (const float*)d_in[1];
    const float* R   = (const float*)d_in[2];
    const float* Wq  = (const float*)d_in[3];
    const float* bq  = (const float*)d_in[4];
    const float* Wk  = (const float*)d_in[5];
    const float* bk  = (const float*)d_in[6];
    const float* Wv  = (const float*)d_in[7];
    const float* bv  = (const float*)d_in[8];
    const float* Wo  = (const float*)d_in[9];
    const float* bo  = (const float*)d_in[10];
    float* out = (float*)d_out;

    __half *pa, *q, *k, *y, *vt, *wq, *wk, *wv, *wo;
    cudaGetSymbolAddress((void**)&pa, g_pa);
    cudaGetSymbolAddress((void**)&q,  g_q16);
    cudaGetSymbolAddress((void**)&k,  g_k16);
    cudaGetSymbolAddress((void**)&y,  g_y16);
    cudaGetSymbolAddress((void**)&vt, g_vT);
    cudaGetSymbolAddress((void**)&wq, g_w16q);
    cudaGetSymbolAddress((void**)&wk, g_w16k);
    cudaGetSymbolAddress((void**)&wv, g_w16v);
    cudaGetSymbolAddress((void**)&wo, g_w16o);

    cudaFuncSetAttribute(gemm16_multi<0>, cudaFuncAttributeMaxDynamicSharedMemorySize, SMEM_TC);
    cudaFuncSetAttribute(gemm16_multi<1>, cudaFuncAttributeMaxDynamicSharedMemorySize, SMEM_TC);
    cudaFuncSetAttribute(gemm16_multi<2>, cudaFuncAttributeMaxDynamicSharedMemorySize, SMEM_TC);
    cudaFuncSetAttribute(gemm16_multi<3>, cudaFuncAttributeMaxDynamicSharedMemorySize, SMEM_TC);
    cudaFuncSetAttribute(flash_kernel,    cudaFuncAttributeMaxDynamicSharedMemorySize, SMEM_FL);

    const int M = Bc * Tc;                   // 4096
    dim3 g3(24, M / 128);
    dim3 g2(16, M / 128);
    dim3 g1(8,  M / 128);
    dim3 gf(Tc / 256, Bc * Hc);              // (4, 64) = 256 CTAs
    dim3 gw(Dc, 4);

    pack16x4_kernel<<<gw, 256>>>(Wq, wq, Wk, wk, Wv, wv, Wo, wo);

    // Stage 1: self-attention (QKV + rope + V-transpose fused)
    pack16_kernel<<<M, 256>>>(x, pa);
    gemm16_multi<0><<<g3, 256, SMEM_TC>>>(pa, wq, wk, wv, bq, bk, bv, q, k, vt, R);
    flash_kernel<<<gf, 256, SMEM_FL>>>(q, k, vt, y);

    // Stage 2: cross-attention
    gemm16_multi<1><<<g1, 256, SMEM_TC>>>(y, wq, wq, wq, bq, bq, bq, q, q, q, R);
    pack16_kernel<<<M, 256>>>(mem, pa);
    gemm16_multi<2><<<g2, 256, SMEM_TC>>>(pa, wk, wv, wv, bk, bv, bv, k, vt, vt, R);
    flash_kernel<<<gf, 256, SMEM_FL>>>(q, k, vt, y);

    // Output projection (fp32 out)
    gemm16_multi<3><<<g1, 256, SMEM_TC>>>(y, wo, wo, wo, bo, bo, bo, out, out, out, R);
}

// round 15
// speedup vs baseline: 1.3482x; 1.3482x over previous
#include <cuda_runtime.h>
#include <cuda_fp16.h>
#include <stdint.h>

// Problem constants
#define Bc   4
#define Tc   1024
#define Lc   1024
#define Dc   1024
#define Hc   16
#define HSc  64
#define ROTc 32

// ---------------- scratch (device globals; no allocation allowed) ----------
__device__ __half g_pa[Bc * Tc * Dc];
__device__ __half g_q16[Bc * Tc * Dc];
__device__ __half g_k16[Bc * Lc * Dc];
__device__ __half g_y16[Bc * Tc * Dc];
__device__ __half g_vT[Bc * Hc * HSc * Lc];
__device__ __half g_w16q[Dc * Dc];
__device__ __half g_w16k[Dc * Dc];
__device__ __half g_w16v[Dc * Dc];
__device__ __half g_w16o[Dc * Dc];

__device__ __forceinline__ uint32_t smem_u32(const void* p) {
    uint32_t a;
    asm("{ .reg .u64 t; cvta.to.shared.u64 t, %1; cvt.u32.u64 %0, t; }" : "=r"(a) : "l"(p));
    return a;
}

#define MMA_F16(acc, a0, a1, a2, a3, b0, b1)                                      \
    asm volatile(                                                                 \
        "mma.sync.aligned.m16n8k16.row.col.f32.f16.f16.f32 "                      \
        "{%0,%1,%2,%3},{%4,%5,%6,%7},{%8,%9},{%0,%1,%2,%3};"                      \
        : "+f"(acc[0]), "+f"(acc[1]), "+f"(acc[2]), "+f"(acc[3])                  \
        : "r"(a0), "r"(a1), "r"(a2), "r"(a3), "r"(b0), "r"(b1))

#define LDSM4(r0, r1, r2, r3, addr)                                               \
    asm volatile("ldmatrix.sync.aligned.m8n8.x4.shared.b16 {%0,%1,%2,%3}, [%4];"  \
        : "=r"(r0), "=r"(r1), "=r"(r2), "=r"(r3) : "r"(addr))

#define CP16(dst, src)                                                            \
    asm volatile("cp.async.cg.shared.global [%0], [%1], 16;" :: "r"(dst), "l"(src))
#define CP_COMMIT() asm volatile("cp.async.commit_group;" ::: "memory")
#define CP_WAIT1()  asm volatile("cp.async.wait_group 1;" ::: "memory")
#define CP_WAIT0()  asm volatile("cp.async.wait_group 0;" ::: "memory")

__device__ __forceinline__ float ex2f(float x) {
    float r;
    asm("ex2.approx.f32 %0, %1;" : "=f"(r) : "f"(x));
    return r;
}

// ---------------------------------------------------------------------------
// pack: fp32 [rows x 1024] -> fp16
// ---------------------------------------------------------------------------
__global__ void pack16_kernel(const float* __restrict__ src, __half* __restrict__ dst) {
    int m = blockIdx.x;
    int c = threadIdx.x * 4;
    float4 v = *(const float4*)(src + (size_t)m * Dc + c);
    __half2* d = (__half2*)(dst + (size_t)m * Dc + c);
    d[0] = __floats2half2_rn(v.x, v.y);
    d[1] = __floats2half2_rn(v.z, v.w);
}

__global__ void pack16x4_kernel(const float* __restrict__ s0, __half* __restrict__ d0,
                                const float* __restrict__ s1, __half* __restrict__ d1,
                                const float* __restrict__ s2, __half* __restrict__ d2,
                                const float* __restrict__ s3, __half* __restrict__ d3) {
    const float* src; __half* dst;
    switch (blockIdx.y) {
        case 0: src = s0; dst = d0; break;
        case 1: src = s1; dst = d1; break;
        case 2: src = s2; dst = d2; break;
        default: src = s3; dst = d3; break;
    }
    int m = blockIdx.x;
    int c = threadIdx.x * 4;
    float4 v = *(const float4*)(src + (size_t)m * Dc + c);
    __half2* d = (__half2*)(dst + (size_t)m * Dc + c);
    d[0] = __floats2half2_rn(v.x, v.y);
    d[1] = __floats2half2_rn(v.z, v.w);
}

// ---------------------------------------------------------------------------
// Multi-output dense GEMM fp16, 64-wide k-tiles (16 iters), 3-stage pipeline,
// fused epilogues. (round-11 config; redundant tail barrier removed)
// MODE 0: QKV stage1 (sel0 q+rope, sel1 k+rope, sel2 v->vT transposed)
// MODE 1: single GEMM fp16 out | MODE 2: KV stage2 | MODE 3: fp32 out
// ---------------------------------------------------------------------------
#define STG_SZ 36864
#define SMEM_TC (3 * STG_SZ)

template <int MODE>
__global__ __launch_bounds__(256, 2) void gemm16_multi(
        const __half* __restrict__ Ap,
        const __half* __restrict__ W0, const __half* __restrict__ W1,
        const __half* __restrict__ W2,
        const float* __restrict__ b0, const float* __restrict__ b1,
        const float* __restrict__ b2,
        void* __restrict__ C0, void* __restrict__ C1, void* __restrict__ C2,
        const float* __restrict__ R) {
    extern __shared__ char smem[];
    const uint32_t sb = smem_u32(smem);

    int sel = 0;
    if (MODE == 0 || MODE == 2) sel = blockIdx.x >> 3;

    const __half* Wp = (sel == 0) ? W0 : (sel == 1 ? W1 : W2);
    const float*  bp = (sel == 0) ? b0 : (sel == 1 ? b1 : b2);
    void*         Cp = (sel == 0) ? C0 : (sel == 1 ? C1 : C2);

    const int n00 = (blockIdx.x & 7) * 128;

    const int tid = threadIdx.x;
    const int lane = tid & 31;
    const int warp = tid >> 5;
    const int g = lane >> 2, tig = lane & 3;
    const int wm = warp >> 2, wn = warp & 3;

    const bool do_rope = (MODE == 0) && (sel < 2) && ((wn & 1) == 0);
    const bool do_vt   = (MODE == 0 && sel == 2) || (MODE == 2 && sel == 1);

    const __half* Arow = Ap + (size_t)(blockIdx.y * 128) * Dc;
    const __half* Brow = Wp + (size_t)n00 * Dc;

    float acc[4][4][4] = {};

#define LOAD_TILE(kt, stage) do {                                                 \
        uint32_t base_ = sb + (stage) * STG_SZ;                                   \
        _Pragma("unroll")                                                         \
        for (int i_ = 0; i_ < 4; ++i_) {                                          \
            int idx_ = tid + i_ * 256;                                            \
            int row_ = idx_ >> 3, cc_ = idx_ & 7;                                 \
            CP16(base_ + row_ * 144 + cc_ * 16,                                   \
                 Arow + (size_t)row_ * Dc + (kt) * 64 + cc_ * 8);                 \
            CP16(base_ + 18432 + row_ * 144 + cc_ * 16,                           \
                 Brow + (size_t)row_ * Dc + (kt) * 64 + cc_ * 8);                 \
        }                                                                         \
        CP_COMMIT();                                                              \
    } while (0)

    LOAD_TILE(0, 0);
    LOAD_TILE(1, 1);

    const int NT = 16;
    int stage = 0;
    for (int kt = 0; kt < NT; ++kt) {
        if (kt + 2 < NT) CP_WAIT1(); else CP_WAIT0();
        __syncthreads();
        if (kt + 2 < NT) {
            int ns = stage + 2; if (ns >= 3) ns -= 3;
            LOAD_TILE(kt + 2, ns);
        }
        const uint32_t Ab = sb + stage * STG_SZ;
        const uint32_t Bb = Ab + 18432;
        const int arow = lane & 15;
        const int acol = (lane >> 4) * 16;
#pragma unroll
        for (int ks = 0; ks < 4; ++ks) {
            uint32_t a[4][4], bt[2][4];
#pragma unroll
            for (int mi = 0; mi < 4; ++mi) {
                uint32_t ad = Ab + (wm * 64 + mi * 16 + arow) * 144 + ks * 32 + acol;
                LDSM4(a[mi][0], a[mi][1], a[mi][2], a[mi][3], ad);
            }
#pragma unroll
            for (int nb = 0; nb < 2; ++nb) {
                uint32_t bd = Bb + (wn * 32 + nb * 16 + arow) * 144 + ks * 32 + acol;
                LDSM4(bt[nb][0], bt[nb][1], bt[nb][2], bt[nb][3], bd);
            }
#pragma unroll
            for (int mi = 0; mi < 4; ++mi)
#pragma unroll
                for (int ni = 0; ni < 4; ++ni)
                    MMA_F16(acc[mi][ni], a[mi][0], a[mi][1], a[mi][2], a[mi][3],
                            bt[ni >> 1][ni & 1], bt[ni >> 1][(ni & 1) + 2]);
        }
        ++stage; if (stage == 3) stage = 0;
        // NOTE: no trailing __syncthreads() — top-of-loop WAIT+sync of the next
        // iteration orders this iteration's smem reads before any overwrite.
    }
#undef LOAD_TILE

#pragma unroll
    for (int mi = 0; mi < 4; ++mi) {
#pragma unroll
        for (int ni = 0; ni < 4; ++ni) {
            int n = n00 + wn * 32 + ni * 8 + 2 * tig;
            float2 bv = *(const float2*)(bp + n);
            acc[mi][ni][0] += bv.x; acc[mi][ni][1] += bv.y;
            acc[mi][ni][2] += bv.x; acc[mi][ni][3] += bv.y;
        }
    }

    if (do_rope) {
#pragma unroll
        for (int mi = 0; mi < 4; ++mi) {
            int m = blockIdx.y * 128 + wm * 64 + mi * 16 + g;
            int t = m & 1023;
#pragma unroll
            for (int ni = 0; ni < 2; ++ni) {
                int p = ni * 8 + 2 * tig;
                float2 cA = *(const float2*)(R + t * ROTc + p);
                float2 sA = *(const float2*)(R + Tc * ROTc + t * ROTc + p);
                float2 cB = *(const float2*)(R + (t + 8) * ROTc + p);
                float2 sB = *(const float2*)(R + Tc * ROTc + (t + 8) * ROTc + p);
                float a0 = acc[mi][ni][0], a1 = acc[mi][ni][1];
                float a2 = acc[mi][ni][2], a3 = acc[mi][ni][3];
                float q0 = acc[mi][ni + 2][0], q1 = acc[mi][ni + 2][1];
                float q2 = acc[mi][ni + 2][2], q3 = acc[mi][ni + 2][3];
                acc[mi][ni][0]     = a0 * cA.x - q0 * sA.x;
                acc[mi][ni + 2][0] = q0 * cA.x + a0 * sA.x;
                acc[mi][ni][1]     = a1 * cA.y - q1 * sA.y;
                acc[mi][ni + 2][1] = q1 * cA.y + a1 * sA.y;
                acc[mi][ni][2]     = a2 * cB.x - q2 * sB.x;
                acc[mi][ni + 2][2] = q2 * cB.x + a2 * sB.x;
                acc[mi][ni][3]     = a3 * cB.y - q3 * sB.y;
                acc[mi][ni + 2][3] = q3 * cB.y + a3 * sB.y;
            }
        }
    }

    if (do_vt) {
        __half* VT = (__half*)Cp;
#pragma unroll
        for (int mi = 0; mi < 4; ++mi) {
            int m = blockIdx.y * 128 + wm * 64 + mi * 16 + g;
            int bb = m >> 10, l = m & 1023;
#pragma unroll
            for (int ni = 0; ni < 4; ++ni) {
                int n = n00 + wn * 32 + ni * 8 + 2 * tig;
                int h = n >> 6, j = n & 63;
                __half* base = VT + ((size_t)((bb * 16 + h) * 64 + j)) * Lc;
                base[l]            = __float2half_rn(acc[mi][ni][0]);
                base[Lc + l]       = __float2half_rn(acc[mi][ni][1]);
                base[l + 8]        = __float2half_rn(acc[mi][ni][2]);
                base[Lc + l + 8]   = __float2half_rn(acc[mi][ni][3]);
            }
        }
    } else if (MODE == 3) {
        float* C = (float*)Cp;
#pragma unroll
        for (int mi = 0; mi < 4; ++mi) {
            int m = blockIdx.y * 128 + wm * 64 + mi * 16 + g;
#pragma unroll
            for (int ni = 0; ni < 4; ++ni) {
                int n = n00 + wn * 32 + ni * 8 + 2 * tig;
                *(float2*)(C + (size_t)m * Dc + n) =
                    make_float2(acc[mi][ni][0], acc[mi][ni][1]);
                *(float2*)(C + (size_t)(m + 8) * Dc + n) =
                    make_float2(acc[mi][ni][2], acc[mi][ni][3]);
            }
        }
    } else {
        __half* C = (__half*)Cp;
#pragma unroll
        for (int mi = 0; mi < 4; ++mi) {
            int m = blockIdx.y * 128 + wm * 64 + mi * 16 + g;
#pragma unroll
            for (int ni = 0; ni < 4; ++ni) {
                int n = n00 + wn * 32 + ni * 8 + 2 * tig;
                *(__half2*)(C + (size_t)m * Dc + n) =
                    __floats2half2_rn(acc[mi][ni][0], acc[mi][ni][1]);
                *(__half2*)(C + (size_t)(m + 8) * Dc + n) =
                    __floats2half2_rn(acc[mi][ni][2], acc[mi][ni][3]);
            }
        }
    }
}

// ---------------------------------------------------------------------------
// Flash attention (round-11 best): CTA = 256 q-rows, 8 warps x 32 rows
// (2 groups of 16); each K/V ldmatrix feeds 4 MMAs.
// smem: Q 256x144 | 2 stages x (K 128x144 + V 64x272).
// ---------------------------------------------------------------------------
#define FL_Q    0
#define FL_KV   36864
#define FL_STG  35840           // K 18432 + V 17408
#define SMEM_FL (36864 + 2 * FL_STG)

__global__ __launch_bounds__(256, 1) void flash_kernel(
        const __half* __restrict__ Q, const __half* __restrict__ K,
        const __half* __restrict__ VT, __half* __restrict__ Y) {
    extern __shared__ char smem[];
    const uint32_t sb = smem_u32(smem);

    const int z = blockIdx.y;
    const int b = z >> 4, h = z & 15;
    const int t0 = blockIdx.x * 256;
    const int tid = threadIdx.x;
    const int lane = tid & 31;
    const int warp = tid >> 5;
    const int g = lane >> 2, tig = lane & 3;
    const int arow = lane & 15;
    const int acol = (lane >> 4) * 16;

    const __half* Qbase = Q  + ((size_t)b * Tc + t0) * Dc + h * HSc;
    const __half* Kbase = K  + (size_t)b * Lc * Dc + h * HSc;
    const __half* Vbase = VT + (size_t)z * HSc * Lc;

    {   // Q tile: 256 rows x 128B (8 CP16 per thread)
#pragma unroll
        for (int i = 0; i < 8; ++i) {
            int idx = tid + i * 256;
            int row = idx >> 3, cc = idx & 7;
            CP16(sb + FL_Q + row * 144 + cc * 16,
                 Qbase + (size_t)row * Dc + cc * 8);
        }
        CP_COMMIT();
    }

#define LOADC(c, st) do {                                                         \
        uint32_t kb_ = sb + FL_KV + (st) * FL_STG;                                \
        uint32_t vb_ = kb_ + 18432;                                               \
        _Pragma("unroll")                                                         \
        for (int i_ = 0; i_ < 4; ++i_) {                                          \
            int idx_ = tid + i_ * 256;                                            \
            int krow_ = idx_ >> 3, kcc_ = idx_ & 7;                               \
            CP16(kb_ + krow_ * 144 + kcc_ * 16,                                   \
                 Kbase + (size_t)((c) * 128 + krow_) * Dc + kcc_ * 8);            \
            int vrow_ = idx_ >> 4, vcc_ = idx_ & 15;                              \
            CP16(vb_ + vrow_ * 272 + vcc_ * 16,                                   \
                 Vbase + (size_t)vrow_ * Lc + (c) * 128 + vcc_ * 8);              \
        }                                                                         \
        CP_COMMIT();                                                              \
    } while (0)

    LOADC(0, 0);
    CP_WAIT0();
    __syncthreads();

    // Q fragments for both 16-row groups; fold 0.125*log2(e)
    uint32_t qa[2][4][4];
#pragma unroll
    for (int G = 0; G < 2; ++G)
#pragma unroll
        for (int kb = 0; kb < 4; ++kb) {
            uint32_t ad = sb + FL_Q + (warp * 32 + G * 16 + arow) * 144 + kb * 32 + acol;
            LDSM4(qa[G][kb][0], qa[G][kb][1], qa[G][kb][2], qa[G][kb][3], ad);
        }
    {
        const __half2 sc = __floats2half2_rn(0.1803368801f, 0.1803368801f);
        const uint32_t scu = *(const uint32_t*)&sc;
#pragma unroll
        for (int G = 0; G < 2; ++G)
#pragma unroll
            for (int kb = 0; kb < 4; ++kb)
#pragma unroll
                for (int r = 0; r < 4; ++r) {
                    __half2 t = __hmul2(*(__half2*)&qa[G][kb][r], *(__half2*)&scu);
                    qa[G][kb][r] = *(uint32_t*)&t;
                }
    }

    float lsum[2][2] = {};
    float acc[2][8][4] = {};

    for (int c = 0; c < 8; ++c) {
        if (c > 0) { CP_WAIT0(); __syncthreads(); }
        if (c + 1 < 8) LOADC(c + 1, (c + 1) & 1);

        const uint32_t Kb = sb + FL_KV + (c & 1) * FL_STG;
        const uint32_t Vb = Kb + 18432;

#pragma unroll
        for (int hh = 0; hh < 2; ++hh) {
            float s[2][8][4] = {};
#pragma unroll
            for (int kb = 0; kb < 4; ++kb) {
#pragma unroll
                for (int nb2 = 0; nb2 < 4; ++nb2) {
                    uint32_t b0, b1, b2, b3;
                    LDSM4(b0, b1, b2, b3,
                          Kb + (hh * 64 + nb2 * 16 + arow) * 144 + kb * 32 + acol);
#pragma unroll
                    for (int G = 0; G < 2; ++G) {
                        MMA_F16(s[G][nb2 * 2],     qa[G][kb][0], qa[G][kb][1],
                                qa[G][kb][2], qa[G][kb][3], b0, b2);
                        MMA_F16(s[G][nb2 * 2 + 1], qa[G][kb][0], qa[G][kb][1],
                                qa[G][kb][2], qa[G][kb][3], b1, b3);
                    }
                }
            }
            uint32_t pa_[2][4][4];
#pragma unroll
            for (int G = 0; G < 2; ++G)
#pragma unroll
                for (int nb = 0; nb < 8; ++nb) {
                    float e0 = ex2f(s[G][nb][0]);
                    float e1 = ex2f(s[G][nb][1]);
                    float e2 = ex2f(s[G][nb][2]);
                    float e3 = ex2f(s[G][nb][3]);
                    lsum[G][0] += e0 + e1; lsum[G][1] += e2 + e3;
                    __half2 p01 = __floats2half2_rn(e0, e1);
                    __half2 p23 = __floats2half2_rn(e2, e3);
                    int kb2 = nb >> 1;
                    if ((nb & 1) == 0) {
                        pa_[G][kb2][0] = *(uint32_t*)&p01;
                        pa_[G][kb2][1] = *(uint32_t*)&p23;
                    } else {
                        pa_[G][kb2][2] = *(uint32_t*)&p01;
                        pa_[G][kb2][3] = *(uint32_t*)&p23;
                    }
                }
#pragma unroll
            for (int kb2 = 0; kb2 < 4; ++kb2) {
#pragma unroll
                for (int jb2 = 0; jb2 < 4; ++jb2) {
                    uint32_t v0, v1, v2, v3;
                    LDSM4(v0, v1, v2, v3,
                          Vb + (jb2 * 16 + arow) * 272 + hh * 128 + kb2 * 32 + acol);
#pragma unroll
                    for (int G = 0; G < 2; ++G) {
                        MMA_F16(acc[G][jb2 * 2],     pa_[G][kb2][0], pa_[G][kb2][1],
                                pa_[G][kb2][2], pa_[G][kb2][3], v0, v2);
                        MMA_F16(acc[G][jb2 * 2 + 1], pa_[G][kb2][0], pa_[G][kb2][1],
                                pa_[G][kb2][2], pa_[G][kb2][3], v1, v3);
                    }
                }
            }
        }
    }
#undef LOADC

#pragma unroll
    for (int G = 0; G < 2; ++G) {
        float l0 = lsum[G][0], l1 = lsum[G][1];
        l0 += __shfl_xor_sync(0xffffffffu, l0, 1);
        l0 += __shfl_xor_sync(0xffffffffu, l0, 2);
        l1 += __shfl_xor_sync(0xffffffffu, l1, 1);
        l1 += __shfl_xor_sync(0xffffffffu, l1, 2);
        const float inv0 = __frcp_rn(l0), inv1 = __frcp_rn(l1);
        __half* Yy = Y + ((size_t)b * Tc + t0 + warp * 32 + G * 16) * Dc + h * HSc;
#pragma unroll
        for (int jnb = 0; jnb < 8; ++jnb) {
            int col = jnb * 8 + 2 * tig;
            *(__half2*)(Yy + (size_t)g * Dc + col) =
                __floats2half2_rn(acc[G][jnb][0] * inv0, acc[G][jnb][1] * inv0);
            *(__half2*)(Yy + (size_t)(g + 8) * Dc + col) =
                __floats2half2_rn(acc[G][jnb][2] * inv1, acc[G][jnb][3] * inv1);
        }
    }
}

// ---------------------------------------------------------------------------
extern "C" void kernel_launch(void* const* d_in, const int* in_sizes, int n_in,
                              void* d_out, int out_size) {
    const float* x   = (const float*)d_in[0];
    const float* mem = (const float*)d_in[1];
    const float* R   = (const float*)d_in[2];
    const float* Wq  = (const float*)d_in[3];
    const float* bq  = (const float*)d_in[4];
    const float* Wk  = (const float*)d_in[5];
    const float* bk  = (const float*)d_in[6];
    const float* Wv  = (const float*)d_in[7];
    const float* bv  = (const float*)d_in[8];
    const float* Wo  = (const float*)d_in[9];
    const float* bo  = (const float*)d_in[10];
    float* out = (float*)d_out;

    __half *pa, *q, *k, *y, *vt, *wq, *wk, *wv, *wo;
    cudaGetSymbolAddress((void**)&pa, g_pa);
    cudaGetSymbolAddress((void**)&q,  g_q16);
    cudaGetSymbolAddress((void**)&k,  g_k16);
    cudaGetSymbolAddress((void**)&y,  g_y16);
    cudaGetSymbolAddress((void**)&vt, g_vT);
    cudaGetSymbolAddress((void**)&wq, g_w16q);
    cudaGetSymbolAddress((void**)&wk, g_w16k);
    cudaGetSymbolAddress((void**)&wv, g_w16v);
    cudaGetSymbolAddress((void**)&wo, g_w16o);

    cudaFuncSetAttribute(gemm16_multi<0>, cudaFuncAttributeMaxDynamicSharedMemorySize, SMEM_TC);
    cudaFuncSetAttribute(gemm16_multi<1>, cudaFuncAttributeMaxDynamicSharedMemorySize, SMEM_TC);
    cudaFuncSetAttribute(gemm16_multi<2>, cudaFuncAttributeMaxDynamicSharedMemorySize, SMEM_TC);
    cudaFuncSetAttribute(gemm16_multi<3>, cudaFuncAttributeMaxDynamicSharedMemorySize, SMEM_TC);
    cudaFuncSetAttribute(flash_kernel,    cudaFuncAttributeMaxDynamicSharedMemorySize, SMEM_FL);

    const int M = Bc * Tc;                   // 4096
    dim3 g3(24, M / 128);
    dim3 g2(16, M / 128);
    dim3 g1(8,  M / 128);
    dim3 gf(Tc / 256, Bc * Hc);              // (4, 64) = 256 CTAs
    dim3 gw(Dc, 4);

    pack16x4_kernel<<<gw, 256>>>(Wq, wq, Wk, wk, Wv, wv, Wo, wo);

    // Stage 1: self-attention (QKV + rope + V-transpose fused)
    pack16_kernel<<<M, 256>>>(x, pa);
    gemm16_multi<0><<<g3, 256, SMEM_TC>>>(pa, wq, wk, wv, bq, bk, bv, q, k, vt, R);
    flash_kernel<<<gf, 256, SMEM_FL>>>(q, k, vt, y);

    // Stage 2: cross-attention
    gemm16_multi<1><<<g1, 256, SMEM_TC>>>(y, wq, wq, wq, bq, bq, bq, q, q, q, R);
    pack16_kernel<<<M, 256>>>(mem, pa);
    gemm16_multi<2><<<g2, 256, SMEM_TC>>>(pa, wk, wv, wv, bk, bv, bv, k, vt, vt, R);
    flash_kernel<<<gf, 256, SMEM_FL>>>(q, k, vt, y);

    // Output projection (fp32 out)
    gemm16_multi<3><<<g1, 256, SMEM_TC>>>(y, wo, wo, wo, bo, bo, bo, out, out, out, R);
}

// round 16
// speedup vs baseline: 1.3871x; 1.0288x over previous
#include <cuda_runtime.h>
#include <cuda_fp16.h>
#include <stdint.h>

// Problem constants
#define Bc   4
#define Tc   1024
#define Lc   1024
#define Dc   1024
#define Hc   16
#define HSc  64
#define ROTc 32

// ---------------- scratch (device globals; no allocation allowed) ----------
__device__ __half g_pa[Bc * Tc * Dc];            // packed x
__device__ __half g_pm[Bc * Lc * Dc];            // packed memory
__device__ __half g_q16[Bc * Tc * Dc];
__device__ __half g_k16[Bc * Lc * Dc];           // stage-1 k
__device__ __half g_k2[Bc * Lc * Dc];            // stage-2 k
__device__ __half g_y16[Bc * Tc * Dc];
__device__ __half g_vT[Bc * Hc * HSc * Lc];      // stage-1 vT
__device__ __half g_vT2[Bc * Hc * HSc * Lc];     // stage-2 vT
__device__ __half g_w16q[Dc * Dc];
__device__ __half g_w16k[Dc * Dc];
__device__ __half g_w16v[Dc * Dc];
__device__ __half g_w16o[Dc * Dc];

__device__ __forceinline__ uint32_t smem_u32(const void* p) {
    uint32_t a;
    asm("{ .reg .u64 t; cvta.to.shared.u64 t, %1; cvt.u32.u64 %0, t; }" : "=r"(a) : "l"(p));
    return a;
}

#define MMA_F16(acc, a0, a1, a2, a3, b0, b1)                                      \
    asm volatile(                                                                 \
        "mma.sync.aligned.m16n8k16.row.col.f32.f16.f16.f32 "                      \
        "{%0,%1,%2,%3},{%4,%5,%6,%7},{%8,%9},{%0,%1,%2,%3};"                      \
        : "+f"(acc[0]), "+f"(acc[1]), "+f"(acc[2]), "+f"(acc[3])                  \
        : "r"(a0), "r"(a1), "r"(a2), "r"(a3), "r"(b0), "r"(b1))

#define LDSM4(r0, r1, r2, r3, addr)                                               \
    asm volatile("ldmatrix.sync.aligned.m8n8.x4.shared.b16 {%0,%1,%2,%3}, [%4];"  \
        : "=r"(r0), "=r"(r1), "=r"(r2), "=r"(r3) : "r"(addr))

#define CP16(dst, src)                                                            \
    asm volatile("cp.async.cg.shared.global [%0], [%1], 16;" :: "r"(dst), "l"(src))
#define CP_COMMIT() asm volatile("cp.async.commit_group;" ::: "memory")
#define CP_WAIT1()  asm volatile("cp.async.wait_group 1;" ::: "memory")
#define CP_WAIT0()  asm volatile("cp.async.wait_group 0;" ::: "memory")

__device__ __forceinline__ float ex2f(float x) {
    float r;
    asm("ex2.approx.f32 %0, %1;" : "=f"(r) : "f"(x));
    return r;
}

// ---------------------------------------------------------------------------
// packs
// ---------------------------------------------------------------------------
__global__ void pack16x2_kernel(const float* __restrict__ s0, __half* __restrict__ d0,
                                const float* __restrict__ s1, __half* __restrict__ d1) {
    const float* src = blockIdx.y ? s1 : s0;
    __half* dst = blockIdx.y ? d1 : d0;
    int m = blockIdx.x;
    int c = threadIdx.x * 4;
    float4 v = *(const float4*)(src + (size_t)m * Dc + c);
    __half2* d = (__half2*)(dst + (size_t)m * Dc + c);
    d[0] = __floats2half2_rn(v.x, v.y);
    d[1] = __floats2half2_rn(v.z, v.w);
}

__global__ void pack16x4_kernel(const float* __restrict__ s0, __half* __restrict__ d0,
                                const float* __restrict__ s1, __half* __restrict__ d1,
                                const float* __restrict__ s2, __half* __restrict__ d2,
                                const float* __restrict__ s3, __half* __restrict__ d3) {
    const float* src; __half* dst;
    switch (blockIdx.y) {
        case 0: src = s0; dst = d0; break;
        case 1: src = s1; dst = d1; break;
        case 2: src = s2; dst = d2; break;
        default: src = s3; dst = d3; break;
    }
    int m = blockIdx.x;
    int c = threadIdx.x * 4;
    float4 v = *(const float4*)(src + (size_t)m * Dc + c);
    __half2* d = (__half2*)(dst + (size_t)m * Dc + c);
    d[0] = __floats2half2_rn(v.x, v.y);
    d[1] = __floats2half2_rn(v.z, v.w);
}

// ---------------------------------------------------------------------------
// GEMM device body (shared by standalone kernel and fat kernel gemm role).
// gx in [0, NWsel*8): sel = gx>>3, n00 = (gx&7)*128. gy = row tile.
// MODE 0: QKV stage1 | MODE 1: fp16 single | MODE 2: KV stage2 | MODE 3: fp32
// ---------------------------------------------------------------------------
#define STG_SZ 36864
#define SMEM_TC (3 * STG_SZ)

template <int MODE>
__device__ __forceinline__ void gemm_body(
        int gx, int gy, char* smem,
        const __half* __restrict__ Ap,
        const __half* __restrict__ W0, const __half* __restrict__ W1,
        const __half* __restrict__ W2,
        const float* __restrict__ b0, const float* __restrict__ b1,
        const float* __restrict__ b2,
        void* __restrict__ C0, void* __restrict__ C1, void* __restrict__ C2,
        const float* __restrict__ R) {
    const uint32_t sb = smem_u32(smem);

    int sel = 0;
    if (MODE == 0 || MODE == 2) sel = gx >> 3;

    const __half* Wp = (sel == 0) ? W0 : (sel == 1 ? W1 : W2);
    const float*  bp = (sel == 0) ? b0 : (sel == 1 ? b1 : b2);
    void*         Cp = (sel == 0) ? C0 : (sel == 1 ? C1 : C2);

    const int n00 = (gx & 7) * 128;

    const int tid = threadIdx.x;
    const int lane = tid & 31;
    const int warp = tid >> 5;
    const int g = lane >> 2, tig = lane & 3;
    const int wm = warp >> 2, wn = warp & 3;

    const bool do_rope = (MODE == 0) && (sel < 2) && ((wn & 1) == 0);
    const bool do_vt   = (MODE == 0 && sel == 2) || (MODE == 2 && sel == 1);

    const __half* Arow = Ap + (size_t)(gy * 128) * Dc;
    const __half* Brow = Wp + (size_t)n00 * Dc;

    float acc[4][4][4] = {};

#define LOAD_TILE_G(kt, stage) do {                                               \
        uint32_t base_ = sb + (stage) * STG_SZ;                                   \
        _Pragma("unroll")                                                         \
        for (int i_ = 0; i_ < 4; ++i_) {                                          \
            int idx_ = tid + i_ * 256;                                            \
            int row_ = idx_ >> 3, cc_ = idx_ & 7;                                 \
            CP16(base_ + row_ * 144 + cc_ * 16,                                   \
                 Arow + (size_t)row_ * Dc + (kt) * 64 + cc_ * 8);                 \
            CP16(base_ + 18432 + row_ * 144 + cc_ * 16,                           \
                 Brow + (size_t)row_ * Dc + (kt) * 64 + cc_ * 8);                 \
        }                                                                         \
        CP_COMMIT();                                                              \
    } while (0)

    LOAD_TILE_G(0, 0);
    LOAD_TILE_G(1, 1);

    const int NT = 16;
    int stage = 0;
    for (int kt = 0; kt < NT; ++kt) {
        if (kt + 2 < NT) CP_WAIT1(); else CP_WAIT0();
        __syncthreads();
        if (kt + 2 < NT) {
            int ns = stage + 2; if (ns >= 3) ns -= 3;
            LOAD_TILE_G(kt + 2, ns);
        }
        const uint32_t Ab = sb + stage * STG_SZ;
        const uint32_t Bb = Ab + 18432;
        const int arow = lane & 15;
        const int acol = (lane >> 4) * 16;
#pragma unroll
        for (int ks = 0; ks < 4; ++ks) {
            uint32_t a[4][4], bt[2][4];
#pragma unroll
            for (int mi = 0; mi < 4; ++mi) {
                uint32_t ad = Ab + (wm * 64 + mi * 16 + arow) * 144 + ks * 32 + acol;
                LDSM4(a[mi][0], a[mi][1], a[mi][2], a[mi][3], ad);
            }
#pragma unroll
            for (int nb = 0; nb < 2; ++nb) {
                uint32_t bd = Bb + (wn * 32 + nb * 16 + arow) * 144 + ks * 32 + acol;
                LDSM4(bt[nb][0], bt[nb][1], bt[nb][2], bt[nb][3], bd);
            }
#pragma unroll
            for (int mi = 0; mi < 4; ++mi)
#pragma unroll
                for (int ni = 0; ni < 4; ++ni)
                    MMA_F16(acc[mi][ni], a[mi][0], a[mi][1], a[mi][2], a[mi][3],
                            bt[ni >> 1][ni & 1], bt[ni >> 1][(ni & 1) + 2]);
        }
        ++stage; if (stage == 3) stage = 0;
    }
#undef LOAD_TILE_G

#pragma unroll
    for (int mi = 0; mi < 4; ++mi) {
#pragma unroll
        for (int ni = 0; ni < 4; ++ni) {
            int n = n00 + wn * 32 + ni * 8 + 2 * tig;
            float2 bv = *(const float2*)(bp + n);
            acc[mi][ni][0] += bv.x; acc[mi][ni][1] += bv.y;
            acc[mi][ni][2] += bv.x; acc[mi][ni][3] += bv.y;
        }
    }

    if (do_rope) {
#pragma unroll
        for (int mi = 0; mi < 4; ++mi) {
            int m = gy * 128 + wm * 64 + mi * 16 + g;
            int t = m & 1023;
#pragma unroll
            for (int ni = 0; ni < 2; ++ni) {
                int p = ni * 8 + 2 * tig;
                float2 cA = *(const float2*)(R + t * ROTc + p);
                float2 sA = *(const float2*)(R + Tc * ROTc + t * ROTc + p);
                float2 cB = *(const float2*)(R + (t + 8) * ROTc + p);
                float2 sB = *(const float2*)(R + Tc * ROTc + (t + 8) * ROTc + p);
                float a0 = acc[mi][ni][0], a1 = acc[mi][ni][1];
                float a2 = acc[mi][ni][2], a3 = acc[mi][ni][3];
                float q0 = acc[mi][ni + 2][0], q1 = acc[mi][ni + 2][1];
                float q2 = acc[mi][ni + 2][2], q3 = acc[mi][ni + 2][3];
                acc[mi][ni][0]     = a0 * cA.x - q0 * sA.x;
                acc[mi][ni + 2][0] = q0 * cA.x + a0 * sA.x;
                acc[mi][ni][1]     = a1 * cA.y - q1 * sA.y;
                acc[mi][ni + 2][1] = q1 * cA.y + a1 * sA.y;
                acc[mi][ni][2]     = a2 * cB.x - q2 * sB.x;
                acc[mi][ni + 2][2] = q2 * cB.x + a2 * sB.x;
                acc[mi][ni][3]     = a3 * cB.y - q3 * sB.y;
                acc[mi][ni + 2][3] = q3 * cB.y + a3 * sB.y;
            }
        }
    }

    if (do_vt) {
        __half* VT = (__half*)Cp;
#pragma unroll
        for (int mi = 0; mi < 4; ++mi) {
            int m = gy * 128 + wm * 64 + mi * 16 + g;
            int bb = m >> 10, l = m & 1023;
#pragma unroll
            for (int ni = 0; ni < 4; ++ni) {
                int n = n00 + wn * 32 + ni * 8 + 2 * tig;
                int h = n >> 6, j = n & 63;
                __half* base = VT + ((size_t)((bb * 16 + h) * 64 + j)) * Lc;
                base[l]            = __float2half_rn(acc[mi][ni][0]);
                base[Lc + l]       = __float2half_rn(acc[mi][ni][1]);
                base[l + 8]        = __float2half_rn(acc[mi][ni][2]);
                base[Lc + l + 8]   = __float2half_rn(acc[mi][ni][3]);
            }
        }
    } else if (MODE == 3) {
        float* C = (float*)Cp;
#pragma unroll
        for (int mi = 0; mi < 4; ++mi) {
            int m = gy * 128 + wm * 64 + mi * 16 + g;
#pragma unroll
            for (int ni = 0; ni < 4; ++ni) {
                int n = n00 + wn * 32 + ni * 8 + 2 * tig;
                *(float2*)(C + (size_t)m * Dc + n) =
                    make_float2(acc[mi][ni][0], acc[mi][ni][1]);
                *(float2*)(C + (size_t)(m + 8) * Dc + n) =
                    make_float2(acc[mi][ni][2], acc[mi][ni][3]);
            }
        }
    } else {
        __half* C = (__half*)Cp;
#pragma unroll
        for (int mi = 0; mi < 4; ++mi) {
            int m = gy * 128 + wm * 64 + mi * 16 + g;
#pragma unroll
            for (int ni = 0; ni < 4; ++ni) {
                int n = n00 + wn * 32 + ni * 8 + 2 * tig;
                *(__half2*)(C + (size_t)m * Dc + n) =
                    __floats2half2_rn(acc[mi][ni][0], acc[mi][ni][1]);
                *(__half2*)(C + (size_t)(m + 8) * Dc + n) =
                    __floats2half2_rn(acc[mi][ni][2], acc[mi][ni][3]);
            }
        }
    }
}

template <int MODE>
__global__ __launch_bounds__(256, 2) void gemm16_multi(
        const __half* __restrict__ Ap,
        const __half* __restrict__ W0, const __half* __restrict__ W1,
        const __half* __restrict__ W2,
        const float* __restrict__ b0, const float* __restrict__ b1,
        const float* __restrict__ b2,
        void* __restrict__ C0, void* __restrict__ C1, void* __restrict__ C2,
        const float* __restrict__ R) {
    extern __shared__ char smem[];
    gemm_body<MODE>(blockIdx.x, blockIdx.y, smem,
                    Ap, W0, W1, W2, b0, b1, b2, C0, C1, C2, R);
}

// ---------------------------------------------------------------------------
// Flash device body (round-10 config: 128 q-rows/CTA, 8 warps x 16 rows).
// fx = t-tile, z = head. smem layout within caller's dynamic smem.
// ---------------------------------------------------------------------------
#define FL_Q    0
#define FL_KV   18432
#define FL_STG  35840           // K 18432 + V 17408
#define SMEM_FL (18432 + 2 * FL_STG)

__device__ __forceinline__ void flash_body(
        int fx, int z, char* smem,
        const __half* __restrict__ Q, const __half* __restrict__ K,
        const __half* __restrict__ VT, __half* __restrict__ Y) {
    const uint32_t sb = smem_u32(smem);

    const int b = z >> 4, h = z & 15;
    const int t0 = fx * 128;
    const int tid = threadIdx.x;
    const int lane = tid & 31;
    const int warp = tid >> 5;
    const int g = lane >> 2, tig = lane & 3;
    const int arow = lane & 15;
    const int acol = (lane >> 4) * 16;

    const __half* Qbase = Q  + ((size_t)b * Tc + t0) * Dc + h * HSc;
    const __half* Kbase = K  + (size_t)b * Lc * Dc + h * HSc;
    const __half* Vbase = VT + (size_t)z * HSc * Lc;

    {
        const int row = tid >> 1;
        const int cc0 = (tid & 1) * 4;
#pragma unroll
        for (int i = 0; i < 4; ++i)
            CP16(sb + FL_Q + row * 144 + (cc0 + i) * 16,
                 Qbase + (size_t)row * Dc + (cc0 + i) * 8);
        CP_COMMIT();
    }

#define LOADC_F(c, st) do {                                                       \
        uint32_t kb_ = sb + FL_KV + (st) * FL_STG;                                \
        uint32_t vb_ = kb_ + 18432;                                               \
        _Pragma("unroll")                                                         \
        for (int i_ = 0; i_ < 4; ++i_) {                                          \
            int idx_ = tid + i_ * 256;                                            \
            int krow_ = idx_ >> 3, kcc_ = idx_ & 7;                               \
            CP16(kb_ + krow_ * 144 + kcc_ * 16,                                   \
                 Kbase + (size_t)((c) * 128 + krow_) * Dc + kcc_ * 8);            \
            int vrow_ = idx_ >> 4, vcc_ = idx_ & 15;                              \
            CP16(vb_ + vrow_ * 272 + vcc_ * 16,                                   \
                 Vbase + (size_t)vrow_ * Lc + (c) * 128 + vcc_ * 8);              \
        }                                                                         \
        CP_COMMIT();                                                              \
    } while (0)

    LOADC_F(0, 0);
    CP_WAIT0();
    __syncthreads();

    uint32_t qa[4][4];
#pragma unroll
    for (int kb = 0; kb < 4; ++kb) {
        uint32_t ad = sb + FL_Q + (warp * 16 + arow) * 144 + kb * 32 + acol;
        LDSM4(qa[kb][0], qa[kb][1], qa[kb][2], qa[kb][3], ad);
    }
    {
        const __half2 sc = __floats2half2_rn(0.1803368801f, 0.1803368801f);
        const uint32_t scu = *(const uint32_t*)&sc;
#pragma unroll
        for (int kb = 0; kb < 4; ++kb)
#pragma unroll
            for (int r = 0; r < 4; ++r) {
                __half2 t = __hmul2(*(__half2*)&qa[kb][r], *(__half2*)&scu);
                qa[kb][r] = *(uint32_t*)&t;
            }
    }

    float l0 = 0.f, l1 = 0.f;
    float acc[8][4] = {};

    for (int c = 0; c < 8; ++c) {
        if (c > 0) { CP_WAIT0(); __syncthreads(); }
        if (c + 1 < 8) LOADC_F(c + 1, (c + 1) & 1);

        const uint32_t Kb = sb + FL_KV + (c & 1) * FL_STG;
        const uint32_t Vb = Kb + 18432;

#pragma unroll
        for (int hh = 0; hh < 2; ++hh) {
            float s[8][4] = {};
#pragma unroll
            for (int kb = 0; kb < 4; ++kb) {
#pragma unroll
                for (int nb2 = 0; nb2 < 4; ++nb2) {
                    uint32_t b0, b1, b2, b3;
                    LDSM4(b0, b1, b2, b3,
                          Kb + (hh * 64 + nb2 * 16 + arow) * 144 + kb * 32 + acol);
                    MMA_F16(s[nb2 * 2],     qa[kb][0], qa[kb][1], qa[kb][2], qa[kb][3], b0, b2);
                    MMA_F16(s[nb2 * 2 + 1], qa[kb][0], qa[kb][1], qa[kb][2], qa[kb][3], b1, b3);
                }
            }
            uint32_t pa_[4][4];
#pragma unroll
            for (int nb = 0; nb < 8; ++nb) {
                float e0 = ex2f(s[nb][0]);
                float e1 = ex2f(s[nb][1]);
                float e2 = ex2f(s[nb][2]);
                float e3 = ex2f(s[nb][3]);
                l0 += e0 + e1; l1 += e2 + e3;
                __half2 p01 = __floats2half2_rn(e0, e1);
                __half2 p23 = __floats2half2_rn(e2, e3);
                int kb2 = nb >> 1;
                if ((nb & 1) == 0) {
                    pa_[kb2][0] = *(uint32_t*)&p01;
                    pa_[kb2][1] = *(uint32_t*)&p23;
                } else {
                    pa_[kb2][2] = *(uint32_t*)&p01;
                    pa_[kb2][3] = *(uint32_t*)&p23;
                }
            }
#pragma unroll
            for (int kb2 = 0; kb2 < 4; ++kb2) {
#pragma unroll
                for (int jb2 = 0; jb2 < 4; ++jb2) {
                    uint32_t v0, v1, v2, v3;
                    LDSM4(v0, v1, v2, v3,
                          Vb + (jb2 * 16 + arow) * 272 + hh * 128 + kb2 * 32 + acol);
                    MMA_F16(acc[jb2 * 2],     pa_[kb2][0], pa_[kb2][1], pa_[kb2][2], pa_[kb2][3], v0, v2);
                    MMA_F16(acc[jb2 * 2 + 1], pa_[kb2][0], pa_[kb2][1], pa_[kb2][2], pa_[kb2][3], v1, v3);
                }
            }
        }
    }
#undef LOADC_F

    l0 += __shfl_xor_sync(0xffffffffu, l0, 1);
    l0 += __shfl_xor_sync(0xffffffffu, l0, 2);
    l1 += __shfl_xor_sync(0xffffffffu, l1, 1);
    l1 += __shfl_xor_sync(0xffffffffu, l1, 2);

    const float inv0 = __frcp_rn(l0), inv1 = __frcp_rn(l1);
    __half* Yy = Y + ((size_t)b * Tc + t0 + warp * 16) * Dc + h * HSc;
#pragma unroll
    for (int jnb = 0; jnb < 8; ++jnb) {
        int col = jnb * 8 + 2 * tig;
        *(__half2*)(Yy + (size_t)g * Dc + col) =
            __floats2half2_rn(acc[jnb][0] * inv0, acc[jnb][1] * inv0);
        *(__half2*)(Yy + (size_t)(g + 8) * Dc + col) =
            __floats2half2_rn(acc[jnb][2] * inv1, acc[jnb][3] * inv1);
    }
}

__global__ __launch_bounds__(256, 2) void flash_kernel(
        const __half* __restrict__ Q, const __half* __restrict__ K,
        const __half* __restrict__ VT, __half* __restrict__ Y) {
    extern __shared__ char smem[];
    flash_body(blockIdx.x, blockIdx.y, smem, Q, K, VT, Y);
}

// ---------------------------------------------------------------------------
// FAT kernel: co-schedules flash stage-1 (512 CTAs) with stage-2 KV GEMM
// (512 CTAs). No data dependency between roles; separate output buffers.
// ---------------------------------------------------------------------------
#define SMEM_FAT SMEM_TC     // 110592 >= SMEM_FL (90112)

__global__ __launch_bounds__(256, 2) void fat_kernel(
        // flash role inputs
        const __half* __restrict__ Q, const __half* __restrict__ K1,
        const __half* __restrict__ VT1, __half* __restrict__ Y,
        // gemm role inputs
        const __half* __restrict__ Pm,
        const __half* __restrict__ Wk, const __half* __restrict__ Wv,
        const float* __restrict__ bk, const float* __restrict__ bv,
        __half* __restrict__ K2, __half* __restrict__ VT2) {
    extern __shared__ char smem[];
    int bid = blockIdx.x;
    if (bid < 512) {
        // KV2 GEMM: virtual grid (16, 32)
        gemm_body<2>(bid & 15, bid >> 4, smem,
                     Pm, Wk, Wv, Wv, bk, bv, bv,
                     (void*)K2, (void*)VT2, (void*)VT2, (const float*)nullptr);
    } else {
        // flash stage-1: virtual grid (8, 64)
        int f = bid - 512;
        flash_body(f & 7, f >> 3, smem, Q, K1, VT1, Y);
    }
}

// ---------------------------------------------------------------------------
extern "C" void kernel_launch(void* const* d_in, const int* in_sizes, int n_in,
                              void* d_out, int out_size) {
    const float* x   = (const float*)d_in[0];
    const float* mem = (const float*)d_in[1];
    const float* R   = (const float*)d_in[2];
    const float* Wq  = (const float*)d_in[3];
    const float* bq  = (const float*)d_in[4];
    const float* Wk  = (const float*)d_in[5];
    const float* bk  = (const float*)d_in[6];
    const float* Wv  = (const float*)d_in[7];
    const float* bv  = (const float*)d_in[8];
    const float* Wo  = (const float*)d_in[9];
    const float* bo  = (const float*)d_in[10];
    float* out = (float*)d_out;

    __half *pa, *pm, *q, *k1, *k2, *y, *vt1, *vt2, *wq, *wk, *wv, *wo;
    cudaGetSymbolAddress((void**)&pa,  g_pa);
    cudaGetSymbolAddress((void**)&pm,  g_pm);
    cudaGetSymbolAddress((void**)&q,   g_q16);
    cudaGetSymbolAddress((void**)&k1,  g_k16);
    cudaGetSymbolAddress((void**)&k2,  g_k2);
    cudaGetSymbolAddress((void**)&y,   g_y16);
    cudaGetSymbolAddress((void**)&vt1, g_vT);
    cudaGetSymbolAddress((void**)&vt2, g_vT2);
    cudaGetSymbolAddress((void**)&wq,  g_w16q);
    cudaGetSymbolAddress((void**)&wk,  g_w16k);
    cudaGetSymbolAddress((void**)&wv,  g_w16v);
    cudaGetSymbolAddress((void**)&wo,  g_w16o);

    cudaFuncSetAttribute(gemm16_multi<0>, cudaFuncAttributeMaxDynamicSharedMemorySize, SMEM_TC);
    cudaFuncSetAttribute(gemm16_multi<1>, cudaFuncAttributeMaxDynamicSharedMemorySize, SMEM_TC);
    cudaFuncSetAttribute(gemm16_multi<3>, cudaFuncAttributeMaxDynamicSharedMemorySize, SMEM_TC);
    cudaFuncSetAttribute(flash_kernel,    cudaFuncAttributeMaxDynamicSharedMemorySize, SMEM_FL);
    cudaFuncSetAttribute(fat_kernel,      cudaFuncAttributeMaxDynamicSharedMemorySize, SMEM_FAT);

    const int M = Bc * Tc;                   // 4096
    dim3 g3(24, M / 128);                    // QKV stage1 (768 CTAs)
    dim3 g1(8,  M / 128);                    // single GEMM (256 CTAs)
    dim3 gf(Tc / 128, Bc * Hc);              // flash (512 CTAs)
    dim3 gfat(1024);                         // fat: 512 gemm + 512 flash
    dim3 gw(Dc, 4);                          // weight pack
    dim3 ga(M, 2);                           // activation pack (x + mem)

    pack16x4_kernel<<<gw, 256>>>(Wq, wq, Wk, wk, Wv, wv, Wo, wo);
    pack16x2_kernel<<<ga, 256>>>(x, pa, mem, pm);

    // Stage 1 QKV (rope + vT fused)
    gemm16_multi<0><<<g3, 256, SMEM_TC>>>(pa, wq, wk, wv, bq, bk, bv, q, k1, vt1, R);

    // flash1 co-scheduled with stage-2 KV GEMM (independent work)
    fat_kernel<<<gfat, 256, SMEM_FAT>>>(q, k1, vt1, y, pm, wk, wv, bk, bv, k2, vt2);

    // Stage 2 q projection (depends on y from flash1)
    gemm16_multi<1><<<g1, 256, SMEM_TC>>>(y, wq, wq, wq, bq, bq, bq, q, q, q, R);

    // flash2
    flash_kernel<<<gf, 256, SMEM_FL>>>(q, k2, vt2, y);

    // Output projection (fp32 out)
    gemm16_multi<3><<<g1, 256, SMEM_TC>>>(y, wo, wo, wo, bo, bo, bo, out, out, out, R);
}

// round 17
// speedup vs baseline: 1.3959x; 1.0063x over previous
#include <cuda_runtime.h>
#include <cuda_fp16.h>
#include <stdint.h>

// Problem constants
#define Bc   4
#define Tc   1024
#define Lc   1024
#define Dc   1024
#define Hc   16
#define HSc  64
#define ROTc 32

// ---------------- scratch (device globals; no allocation allowed) ----------
__device__ __half g_pa[Bc * Tc * Dc];            // packed x
__device__ __half g_pm[Bc * Lc * Dc];            // packed memory
__device__ __half g_q16[Bc * Tc * Dc];           // stage-1 q
__device__ __half g_k16[Bc * Lc * Dc];           // stage-1 k
__device__ __half g_k2[Bc * Lc * Dc];            // stage-2 k
__device__ __half g_y16[Bc * Tc * Dc];
__device__ __half g_vT[Bc * Hc * HSc * Lc];      // stage-1 vT
__device__ __half g_vT2[Bc * Hc * HSc * Lc];     // stage-2 vT
__device__ __half g_w16q[Dc * Dc];
__device__ __half g_w16k[Dc * Dc];
__device__ __half g_w16v[Dc * Dc];
__device__ __half g_w16o[Dc * Dc];

__device__ __forceinline__ uint32_t smem_u32(const void* p) {
    uint32_t a;
    asm("{ .reg .u64 t; cvta.to.shared.u64 t, %1; cvt.u32.u64 %0, t; }" : "=r"(a) : "l"(p));
    return a;
}

#define MMA_F16(acc, a0, a1, a2, a3, b0, b1)                                      \
    asm volatile(                                                                 \
        "mma.sync.aligned.m16n8k16.row.col.f32.f16.f16.f32 "                      \
        "{%0,%1,%2,%3},{%4,%5,%6,%7},{%8,%9},{%0,%1,%2,%3};"                      \
        : "+f"(acc[0]), "+f"(acc[1]), "+f"(acc[2]), "+f"(acc[3])                  \
        : "r"(a0), "r"(a1), "r"(a2), "r"(a3), "r"(b0), "r"(b1))

#define LDSM4(r0, r1, r2, r3, addr)                                               \
    asm volatile("ldmatrix.sync.aligned.m8n8.x4.shared.b16 {%0,%1,%2,%3}, [%4];"  \
        : "=r"(r0), "=r"(r1), "=r"(r2), "=r"(r3) : "r"(addr))

#define CP16(dst, src)                                                            \
    asm volatile("cp.async.cg.shared.global [%0], [%1], 16;" :: "r"(dst), "l"(src))
#define CP_COMMIT() asm volatile("cp.async.commit_group;" ::: "memory")
#define CP_WAIT1()  asm volatile("cp.async.wait_group 1;" ::: "memory")
#define CP_WAIT0()  asm volatile("cp.async.wait_group 0;" ::: "memory")

__device__ __forceinline__ float ex2f(float x) {
    float r;
    asm("ex2.approx.f32 %0, %1;" : "=f"(r) : "f"(x));
    return r;
}

// ---------------------------------------------------------------------------
// packs
// ---------------------------------------------------------------------------
__global__ void pack16x2_kernel(const float* __restrict__ s0, __half* __restrict__ d0,
                                const float* __restrict__ s1, __half* __restrict__ d1) {
    const float* src = blockIdx.y ? s1 : s0;
    __half* dst = blockIdx.y ? d1 : d0;
    int m = blockIdx.x;
    int c = threadIdx.x * 4;
    float4 v = *(const float4*)(src + (size_t)m * Dc + c);
    __half2* d = (__half2*)(dst + (size_t)m * Dc + c);
    d[0] = __floats2half2_rn(v.x, v.y);
    d[1] = __floats2half2_rn(v.z, v.w);
}

__global__ void pack16x4_kernel(const float* __restrict__ s0, __half* __restrict__ d0,
                                const float* __restrict__ s1, __half* __restrict__ d1,
                                const float* __restrict__ s2, __half* __restrict__ d2,
                                const float* __restrict__ s3, __half* __restrict__ d3) {
    const float* src; __half* dst;
    switch (blockIdx.y) {
        case 0: src = s0; dst = d0; break;
        case 1: src = s1; dst = d1; break;
        case 2: src = s2; dst = d2; break;
        default: src = s3; dst = d3; break;
    }
    int m = blockIdx.x;
    int c = threadIdx.x * 4;
    float4 v = *(const float4*)(src + (size_t)m * Dc + c);
    __half2* d = (__half2*)(dst + (size_t)m * Dc + c);
    d[0] = __floats2half2_rn(v.x, v.y);
    d[1] = __floats2half2_rn(v.z, v.w);
}

// ---------------------------------------------------------------------------
// GEMM device body (shared). gx: sel = gx>>3, n00 = (gx&7)*128. gy = row tile.
// MODE 0: QKV stage1 | MODE 2: KV stage2 | MODE 3: fp32 single
// ---------------------------------------------------------------------------
#define STG_SZ 36864
#define SMEM_TC (3 * STG_SZ)

template <int MODE>
__device__ __forceinline__ void gemm_body(
        int gx, int gy, char* smem,
        const __half* __restrict__ Ap,
        const __half* __restrict__ W0, const __half* __restrict__ W1,
        const __half* __restrict__ W2,
        const float* __restrict__ b0, const float* __restrict__ b1,
        const float* __restrict__ b2,
        void* __restrict__ C0, void* __restrict__ C1, void* __restrict__ C2,
        const float* __restrict__ R) {
    const uint32_t sb = smem_u32(smem);

    int sel = 0;
    if (MODE == 0 || MODE == 2) sel = gx >> 3;

    const __half* Wp = (sel == 0) ? W0 : (sel == 1 ? W1 : W2);
    const float*  bp = (sel == 0) ? b0 : (sel == 1 ? b1 : b2);
    void*         Cp = (sel == 0) ? C0 : (sel == 1 ? C1 : C2);

    const int n00 = (gx & 7) * 128;

    const int tid = threadIdx.x;
    const int lane = tid & 31;
    const int warp = tid >> 5;
    const int g = lane >> 2, tig = lane & 3;
    const int wm = warp >> 2, wn = warp & 3;

    const bool do_rope = (MODE == 0) && (sel < 2) && ((wn & 1) == 0);
    const bool do_vt   = (MODE == 0 && sel == 2) || (MODE == 2 && sel == 1);

    const __half* Arow = Ap + (size_t)(gy * 128) * Dc;
    const __half* Brow = Wp + (size_t)n00 * Dc;

    float acc[4][4][4] = {};

#define LOAD_TILE_G(kt, stage) do {                                               \
        uint32_t base_ = sb + (stage) * STG_SZ;                                   \
        _Pragma("unroll")                                                         \
        for (int i_ = 0; i_ < 4; ++i_) {                                          \
            int idx_ = tid + i_ * 256;                                            \
            int row_ = idx_ >> 3, cc_ = idx_ & 7;                                 \
            CP16(base_ + row_ * 144 + cc_ * 16,                                   \
                 Arow + (size_t)row_ * Dc + (kt) * 64 + cc_ * 8);                 \
            CP16(base_ + 18432 + row_ * 144 + cc_ * 16,                           \
                 Brow + (size_t)row_ * Dc + (kt) * 64 + cc_ * 8);                 \
        }                                                                         \
        CP_COMMIT();                                                              \
    } while (0)

    LOAD_TILE_G(0, 0);
    LOAD_TILE_G(1, 1);

    const int NT = 16;
    int stage = 0;
    for (int kt = 0; kt < NT; ++kt) {
        if (kt + 2 < NT) CP_WAIT1(); else CP_WAIT0();
        __syncthreads();
        if (kt + 2 < NT) {
            int ns = stage + 2; if (ns >= 3) ns -= 3;
            LOAD_TILE_G(kt + 2, ns);
        }
        const uint32_t Ab = sb + stage * STG_SZ;
        const uint32_t Bb = Ab + 18432;
        const int arow = lane & 15;
        const int acol = (lane >> 4) * 16;
#pragma unroll
        for (int ks = 0; ks < 4; ++ks) {
            uint32_t a[4][4], bt[2][4];
#pragma unroll
            for (int mi = 0; mi < 4; ++mi) {
                uint32_t ad = Ab + (wm * 64 + mi * 16 + arow) * 144 + ks * 32 + acol;
                LDSM4(a[mi][0], a[mi][1], a[mi][2], a[mi][3], ad);
            }
#pragma unroll
            for (int nb = 0; nb < 2; ++nb) {
                uint32_t bd = Bb + (wn * 32 + nb * 16 + arow) * 144 + ks * 32 + acol;
                LDSM4(bt[nb][0], bt[nb][1], bt[nb][2], bt[nb][3], bd);
            }
#pragma unroll
            for (int mi = 0; mi < 4; ++mi)
#pragma unroll
                for (int ni = 0; ni < 4; ++ni)
                    MMA_F16(acc[mi][ni], a[mi][0], a[mi][1], a[mi][2], a[mi][3],
                            bt[ni >> 1][ni & 1], bt[ni >> 1][(ni & 1) + 2]);
        }
        ++stage; if (stage == 3) stage = 0;
    }
#undef LOAD_TILE_G

#pragma unroll
    for (int mi = 0; mi < 4; ++mi) {
#pragma unroll
        for (int ni = 0; ni < 4; ++ni) {
            int n = n00 + wn * 32 + ni * 8 + 2 * tig;
            float2 bv = *(const float2*)(bp + n);
            acc[mi][ni][0] += bv.x; acc[mi][ni][1] += bv.y;
            acc[mi][ni][2] += bv.x; acc[mi][ni][3] += bv.y;
        }
    }

    if (do_rope) {
#pragma unroll
        for (int mi = 0; mi < 4; ++mi) {
            int m = gy * 128 + wm * 64 + mi * 16 + g;
            int t = m & 1023;
#pragma unroll
            for (int ni = 0; ni < 2; ++ni) {
                int p = ni * 8 + 2 * tig;
                float2 cA = *(const float2*)(R + t * ROTc + p);
                float2 sA = *(const float2*)(R + Tc * ROTc + t * ROTc + p);
                float2 cB = *(const float2*)(R + (t + 8) * ROTc + p);
                float2 sB = *(const float2*)(R + Tc * ROTc + (t + 8) * ROTc + p);
                float a0 = acc[mi][ni][0], a1 = acc[mi][ni][1];
                float a2 = acc[mi][ni][2], a3 = acc[mi][ni][3];
                float q0 = acc[mi][ni + 2][0], q1 = acc[mi][ni + 2][1];
                float q2 = acc[mi][ni + 2][2], q3 = acc[mi][ni + 2][3];
                acc[mi][ni][0]     = a0 * cA.x - q0 * sA.x;
                acc[mi][ni + 2][0] = q0 * cA.x + a0 * sA.x;
                acc[mi][ni][1]     = a1 * cA.y - q1 * sA.y;
                acc[mi][ni + 2][1] = q1 * cA.y + a1 * sA.y;
                acc[mi][ni][2]     = a2 * cB.x - q2 * sB.x;
                acc[mi][ni + 2][2] = q2 * cB.x + a2 * sB.x;
                acc[mi][ni][3]     = a3 * cB.y - q3 * sB.y;
                acc[mi][ni + 2][3] = q3 * cB.y + a3 * sB.y;
            }
        }
    }

    if (do_vt) {
        __half* VT = (__half*)Cp;
#pragma unroll
        for (int mi = 0; mi < 4; ++mi) {
            int m = gy * 128 + wm * 64 + mi * 16 + g;
            int bb = m >> 10, l = m & 1023;
#pragma unroll
            for (int ni = 0; ni < 4; ++ni) {
                int n = n00 + wn * 32 + ni * 8 + 2 * tig;
                int h = n >> 6, j = n & 63;
                __half* base = VT + ((size_t)((bb * 16 + h) * 64 + j)) * Lc;
                base[l]            = __float2half_rn(acc[mi][ni][0]);
                base[Lc + l]       = __float2half_rn(acc[mi][ni][1]);
                base[l + 8]        = __float2half_rn(acc[mi][ni][2]);
                base[Lc + l + 8]   = __float2half_rn(acc[mi][ni][3]);
            }
        }
    } else if (MODE == 3) {
        float* C = (float*)Cp;
#pragma unroll
        for (int mi = 0; mi < 4; ++mi) {
            int m = gy * 128 + wm * 64 + mi * 16 + g;
#pragma unroll
            for (int ni = 0; ni < 4; ++ni) {
                int n = n00 + wn * 32 + ni * 8 + 2 * tig;
                *(float2*)(C + (size_t)m * Dc + n) =
                    make_float2(acc[mi][ni][0], acc[mi][ni][1]);
                *(float2*)(C + (size_t)(m + 8) * Dc + n) =
                    make_float2(acc[mi][ni][2], acc[mi][ni][3]);
            }
        }
    } else {
        __half* C = (__half*)Cp;
#pragma unroll
        for (int mi = 0; mi < 4; ++mi) {
            int m = gy * 128 + wm * 64 + mi * 16 + g;
#pragma unroll
            for (int ni = 0; ni < 4; ++ni) {
                int n = n00 + wn * 32 + ni * 8 + 2 * tig;
                *(__half2*)(C + (size_t)m * Dc + n) =
                    __floats2half2_rn(acc[mi][ni][0], acc[mi][ni][1]);
                *(__half2*)(C + (size_t)(m + 8) * Dc + n) =
                    __floats2half2_rn(acc[mi][ni][2], acc[mi][ni][3]);
            }
        }
    }
}

template <int MODE>
__global__ __launch_bounds__(256, 2) void gemm16_multi(
        const __half* __restrict__ Ap,
        const __half* __restrict__ W0, const __half* __restrict__ W1,
        const __half* __restrict__ W2,
        const float* __restrict__ b0, const float* __restrict__ b1,
        const float* __restrict__ b2,
        void* __restrict__ C0, void* __restrict__ C1, void* __restrict__ C2,
        const float* __restrict__ R) {
    extern __shared__ char smem[];
    gemm_body<MODE>(blockIdx.x, blockIdx.y, smem,
                    Ap, W0, W1, W2, b0, b1, b2, C0, C1, C2, R);
}

// ---------------------------------------------------------------------------
// Flash main loop (shared device body). qa pre-scaled fragments in registers.
// smem stages at FL_KV; writes Y.
// ---------------------------------------------------------------------------
#define FL_Q    0
#define FL_KV   18432
#define FL_STG  35840           // K 18432 + V 17408
#define SMEM_FL (18432 + 2 * FL_STG)

__device__ __forceinline__ void flash_main(
        uint32_t sb, int b, int h, int t0, uint32_t qa[4][4],
        const __half* __restrict__ K, const __half* __restrict__ VT,
        __half* __restrict__ Y) {
    const int tid = threadIdx.x;
    const int lane = tid & 31;
    const int warp = tid >> 5;
    const int g = lane >> 2, tig = lane & 3;
    const int arow = lane & 15;
    const int acol = (lane >> 4) * 16;

    const __half* Kbase = K  + (size_t)b * Lc * Dc + h * HSc;
    const __half* Vbase = VT + (size_t)((b * 16 + h)) * HSc * Lc;

#define LOADC_F(c, st) do {                                                       \
        uint32_t kb_ = sb + FL_KV + (st) * FL_STG;                                \
        uint32_t vb_ = kb_ + 18432;                                               \
        _Pragma("unroll")                                                         \
        for (int i_ = 0; i_ < 4; ++i_) {                                          \
            int idx_ = tid + i_ * 256;                                            \
            int krow_ = idx_ >> 3, kcc_ = idx_ & 7;                               \
            CP16(kb_ + krow_ * 144 + kcc_ * 16,                                   \
                 Kbase + (size_t)((c) * 128 + krow_) * Dc + kcc_ * 8);            \
            int vrow_ = idx_ >> 4, vcc_ = idx_ & 15;                              \
            CP16(vb_ + vrow_ * 272 + vcc_ * 16,                                   \
                 Vbase + (size_t)vrow_ * Lc + (c) * 128 + vcc_ * 8);              \
        }                                                                         \
        CP_COMMIT();                                                              \
    } while (0)

    float l0 = 0.f, l1 = 0.f;
    float acc[8][4] = {};

    LOADC_F(0, 0);

    for (int c = 0; c < 8; ++c) {
        CP_WAIT0();
        __syncthreads();
        if (c + 1 < 8) LOADC_F(c + 1, (c + 1) & 1);

        const uint32_t Kb = sb + FL_KV + (c & 1) * FL_STG;
        const uint32_t Vb = Kb + 18432;

#pragma unroll
        for (int hh = 0; hh < 2; ++hh) {
            float s[8][4] = {};
#pragma unroll
            for (int kb = 0; kb < 4; ++kb) {
#pragma unroll
                for (int nb2 = 0; nb2 < 4; ++nb2) {
                    uint32_t b0, b1, b2, b3;
                    LDSM4(b0, b1, b2, b3,
                          Kb + (hh * 64 + nb2 * 16 + arow) * 144 + kb * 32 + acol);
                    MMA_F16(s[nb2 * 2],     qa[kb][0], qa[kb][1], qa[kb][2], qa[kb][3], b0, b2);
                    MMA_F16(s[nb2 * 2 + 1], qa[kb][0], qa[kb][1], qa[kb][2], qa[kb][3], b1, b3);
                }
            }
            uint32_t pa_[4][4];
#pragma unroll
            for (int nb = 0; nb < 8; ++nb) {
                float e0 = ex2f(s[nb][0]);
                float e1 = ex2f(s[nb][1]);
                float e2 = ex2f(s[nb][2]);
                float e3 = ex2f(s[nb][3]);
                l0 += e0 + e1; l1 += e2 + e3;
                __half2 p01 = __floats2half2_rn(e0, e1);
                __half2 p23 = __floats2half2_rn(e2, e3);
                int kb2 = nb >> 1;
                if ((nb & 1) == 0) {
                    pa_[kb2][0] = *(uint32_t*)&p01;
                    pa_[kb2][1] = *(uint32_t*)&p23;
                } else {
                    pa_[kb2][2] = *(uint32_t*)&p01;
                    pa_[kb2][3] = *(uint32_t*)&p23;
                }
            }
#pragma unroll
            for (int kb2 = 0; kb2 < 4; ++kb2) {
#pragma unroll
                for (int jb2 = 0; jb2 < 4; ++jb2) {
                    uint32_t v0, v1, v2, v3;
                    LDSM4(v0, v1, v2, v3,
                          Vb + (jb2 * 16 + arow) * 272 + hh * 128 + kb2 * 32 + acol);
                    MMA_F16(acc[jb2 * 2],     pa_[kb2][0], pa_[kb2][1], pa_[kb2][2], pa_[kb2][3], v0, v2);
                    MMA_F16(acc[jb2 * 2 + 1], pa_[kb2][0], pa_[kb2][1], pa_[kb2][2], pa_[kb2][3], v1, v3);
                }
            }
        }
    }
#undef LOADC_F

    l0 += __shfl_xor_sync(0xffffffffu, l0, 1);
    l0 += __shfl_xor_sync(0xffffffffu, l0, 2);
    l1 += __shfl_xor_sync(0xffffffffu, l1, 1);
    l1 += __shfl_xor_sync(0xffffffffu, l1, 2);

    const float inv0 = __frcp_rn(l0), inv1 = __frcp_rn(l1);
    __half* Yy = Y + ((size_t)b * Tc + t0 + warp * 16) * Dc + h * HSc;
#pragma unroll
    for (int jnb = 0; jnb < 8; ++jnb) {
        int col = jnb * 8 + 2 * tig;
        *(__half2*)(Yy + (size_t)g * Dc + col) =
            __floats2half2_rn(acc[jnb][0] * inv0, acc[jnb][1] * inv0);
        *(__half2*)(Yy + (size_t)(g + 8) * Dc + col) =
            __floats2half2_rn(acc[jnb][2] * inv1, acc[jnb][3] * inv1);
    }
}

// flash with q loaded from gmem (stage 1; used inside fat kernel)
__device__ __forceinline__ void flash_body(
        int fx, int z, char* smem,
        const __half* __restrict__ Q, const __half* __restrict__ K,
        const __half* __restrict__ VT, __half* __restrict__ Y) {
    const uint32_t sb = smem_u32(smem);
    const int b = z >> 4, h = z & 15;
    const int t0 = fx * 128;
    const int tid = threadIdx.x;
    const int lane = tid & 31;
    const int warp = tid >> 5;
    const int arow = lane & 15;
    const int acol = (lane >> 4) * 16;

    const __half* Qbase = Q + ((size_t)b * Tc + t0) * Dc + h * HSc;
    {
        const int row = tid >> 1;
        const int cc0 = (tid & 1) * 4;
#pragma unroll
        for (int i = 0; i < 4; ++i)
            CP16(sb + FL_Q + row * 144 + (cc0 + i) * 16,
                 Qbase + (size_t)row * Dc + (cc0 + i) * 8);
        CP_COMMIT();
    }
    CP_WAIT0();
    __syncthreads();

    uint32_t qa[4][4];
#pragma unroll
    for (int kb = 0; kb < 4; ++kb) {
        uint32_t ad = sb + FL_Q + (warp * 16 + arow) * 144 + kb * 32 + acol;
        LDSM4(qa[kb][0], qa[kb][1], qa[kb][2], qa[kb][3], ad);
    }
    {
        const __half2 sc = __floats2half2_rn(0.1803368801f, 0.1803368801f);
        const uint32_t scu = *(const uint32_t*)&sc;
#pragma unroll
        for (int kb = 0; kb < 4; ++kb)
#pragma unroll
            for (int r = 0; r < 4; ++r) {
                __half2 t = __hmul2(*(__half2*)&qa[kb][r], *(__half2*)&scu);
                qa[kb][r] = *(uint32_t*)&t;
            }
    }
    __syncthreads();
    flash_main(sb, b, h, t0, qa, K, VT, Y);
}

// ---------------------------------------------------------------------------
// FAT kernel: flash stage-1 (512 CTAs) + stage-2 KV GEMM (512 CTAs).
// ---------------------------------------------------------------------------
#define SMEM_FAT SMEM_TC

__global__ __launch_bounds__(256, 2) void fat_kernel(
        const __half* __restrict__ Q, const __half* __restrict__ K1,
        const __half* __restrict__ VT1, __half* __restrict__ Y,
        const __half* __restrict__ Pm,
        const __half* __restrict__ Wk, const __half* __restrict__ Wv,
        const float* __restrict__ bk, const float* __restrict__ bv,
        __half* __restrict__ K2, __half* __restrict__ VT2) {
    extern __shared__ char smem[];
    int bid = blockIdx.x;
    if (bid < 512) {
        gemm_body<2>(bid & 15, bid >> 4, smem,
                     Pm, Wk, Wv, Wv, bk, bv, bv,
                     (void*)K2, (void*)VT2, (void*)VT2, (const float*)nullptr);
    } else {
        int f = bid - 512;
        flash_body(f & 7, f >> 3, smem, Q, K1, VT1, Y);
    }
}

// ---------------------------------------------------------------------------
// flash2q: q-projection fused into flash stage-2 prologue.
// Prologue computes q tile = Yin[t0..t0+127] . Wq[h*64..h*64+63]^T + bq,
// converted in-register to A-fragments (no gmem roundtrip for q).
// ---------------------------------------------------------------------------
__global__ __launch_bounds__(256, 2) void flash2q_kernel(
        const __half* __restrict__ Yin,
        const __half* __restrict__ Wq, const float* __restrict__ bq,
        const __half* __restrict__ K, const __half* __restrict__ VT,
        __half* __restrict__ Yout) {
    extern __shared__ char smem[];
    const uint32_t sb = smem_u32(smem);

    const int z = blockIdx.y;
    const int b = z >> 4, h = z & 15;
    const int t0 = blockIdx.x * 128;
    const int tid = threadIdx.x;
    const int lane = tid & 31;
    const int warp = tid >> 5;
    const int tig = lane & 3;
    const int arow = lane & 15;
    const int acol = (lane >> 4) * 16;

    const __half* Arow = Yin + ((size_t)b * Tc + t0) * Dc;   // 128 t-rows
    const __half* Brow = Wq + (size_t)(h * HSc) * Dc;        // 64 n-rows

    // ---- q-projection prologue: acc over K=1024 in 16 tiles of 64 ----
#define LOADQ(kt, st) do {                                                        \
        uint32_t ab_ = sb + FL_KV + (st) * FL_STG;                                \
        uint32_t bb_ = ab_ + 18432;                                               \
        _Pragma("unroll")                                                         \
        for (int i_ = 0; i_ < 4; ++i_) {                                          \
            int idx_ = tid + i_ * 256;                                            \
            int row_ = idx_ >> 3, cc_ = idx_ & 7;                                 \
            CP16(ab_ + row_ * 144 + cc_ * 16,                                     \
                 Arow + (size_t)row_ * Dc + (kt) * 64 + cc_ * 8);                 \
        }                                                                         \
        _Pragma("unroll")                                                         \
        for (int i_ = 0; i_ < 2; ++i_) {                                          \
            int idx_ = tid + i_ * 256;                                            \
            int row_ = idx_ >> 3, cc_ = idx_ & 7;                                 \
            CP16(bb_ + row_ * 144 + cc_ * 16,                                     \
                 Brow + (size_t)row_ * Dc + (kt) * 64 + cc_ * 8);                 \
        }                                                                         \
        CP_COMMIT();                                                              \
    } while (0)

    float qacc[8][4] = {};

    LOADQ(0, 0);
    for (int kt = 0; kt < 16; ++kt) {
        CP_WAIT0();
        __syncthreads();
        if (kt + 1 < 16) LOADQ(kt + 1, (kt + 1) & 1);
        const uint32_t Ab = sb + FL_KV + (kt & 1) * FL_STG;
        const uint32_t Bb = Ab + 18432;
#pragma unroll
        for (int ks = 0; ks < 4; ++ks) {
            uint32_t a0, a1, a2, a3;
            LDSM4(a0, a1, a2, a3,
                  Ab + (warp * 16 + arow) * 144 + ks * 32 + acol);
#pragma unroll
            for (int nb = 0; nb < 4; ++nb) {
                uint32_t b0, b1, b2, b3;
                LDSM4(b0, b1, b2, b3,
                      Bb + (nb * 16 + arow) * 144 + ks * 32 + acol);
                MMA_F16(qacc[nb * 2],     a0, a1, a2, a3, b0, b2);
                MMA_F16(qacc[nb * 2 + 1], a0, a1, a2, a3, b1, b3);
            }
        }
        __syncthreads();
    }
#undef LOADQ

    // ---- bias + scale + fp16 convert: C-fragments -> A-fragments ----
    uint32_t qa[4][4];
    {
        const float qs = 0.1803368801f;   // 0.125 * log2(e)
#pragma unroll
        for (int kb = 0; kb < 4; ++kb) {
            int n0 = (2 * kb) * 8 + 2 * tig;
            int n1 = n0 + 8;
            float2 bv0 = *(const float2*)(bq + h * HSc + n0);
            float2 bv1 = *(const float2*)(bq + h * HSc + n1);
            __half2 t;
            t = __floats2half2_rn((qacc[2 * kb][0] + bv0.x) * qs,
                                  (qacc[2 * kb][1] + bv0.y) * qs);
            qa[kb][0] = *(uint32_t*)&t;
            t = __floats2half2_rn((qacc[2 * kb][2] + bv0.x) * qs,
                                  (qacc[2 * kb][3] + bv0.y) * qs);
            qa[kb][1] = *(uint32_t*)&t;
            t = __floats2half2_rn((qacc[2 * kb + 1][0] + bv1.x) * qs,
                                  (qacc[2 * kb + 1][1] + bv1.y) * qs);
            qa[kb][2] = *(uint32_t*)&t;
            t = __floats2half2_rn((qacc[2 * kb + 1][2] + bv1.x) * qs,
                                  (qacc[2 * kb + 1][3] + bv1.y) * qs);
            qa[kb][3] = *(uint32_t*)&t;
        }
    }

    flash_main(sb, b, h, t0, qa, K, VT, Yout);
}

// ---------------------------------------------------------------------------
extern "C" void kernel_launch(void* const* d_in, const int* in_sizes, int n_in,
                              void* d_out, int out_size) {
    const float* x   = (const float*)d_in[0];
    const float* mem = (const float*)d_in[1];
    const float* R   = (const float*)d_in[2];
    const float* Wq  = (const float*)d_in[3];
    const float* bq  = (const float*)d_in[4];
    const float* Wk  = (const float*)d_in[5];
    const float* bk  = (const float*)d_in[6];
    const float* Wv  = (const float*)d_in[7];
    const float* bv  = (const float*)d_in[8];
    const float* Wo  = (const float*)d_in[9];
    const float* bo  = (const float*)d_in[10];
    float* out = (float*)d_out;

    __half *pa, *pm, *q, *k1, *k2, *y, *vt1, *vt2, *wq, *wk, *wv, *wo;
    cudaGetSymbolAddress((void**)&pa,  g_pa);
    cudaGetSymbolAddress((void**)&pm,  g_pm);
    cudaGetSymbolAddress((void**)&q,   g_q16);
    cudaGetSymbolAddress((void**)&k1,  g_k16);
    cudaGetSymbolAddress((void**)&k2,  g_k2);
    cudaGetSymbolAddress((void**)&y,   g_y16);
    cudaGetSymbolAddress((void**)&vt1, g_vT);
    cudaGetSymbolAddress((void**)&vt2, g_vT2);
    cudaGetSymbolAddress((void**)&wq,  g_w16q);
    cudaGetSymbolAddress((void**)&wk,  g_w16k);
    cudaGetSymbolAddress((void**)&wv,  g_w16v);
    cudaGetSymbolAddress((void**)&wo,  g_w16o);

    cudaFuncSetAttribute(gemm16_multi<0>, cudaFuncAttributeMaxDynamicSharedMemorySize, SMEM_TC);
    cudaFuncSetAttribute(gemm16_multi<3>, cudaFuncAttributeMaxDynamicSharedMemorySize, SMEM_TC);
    cudaFuncSetAttribute(fat_kernel,      cudaFuncAttributeMaxDynamicSharedMemorySize, SMEM_FAT);
    cudaFuncSetAttribute(flash2q_kernel,  cudaFuncAttributeMaxDynamicSharedMemorySize, SMEM_FL);

    const int M = Bc * Tc;                   // 4096
    dim3 g3(24, M / 128);                    // QKV stage1 (768 CTAs)
    dim3 g1(8,  M / 128);                    // out GEMM (256 CTAs)
    dim3 gf(Tc / 128, Bc * Hc);              // flash2q (512 CTAs)
    dim3 gfat(1024);                         // fat: 512 gemm + 512 flash
    dim3 gw(Dc, 4);                          // weight pack
    dim3 ga(M, 2);                           // activation pack (x + mem)

    pack16x4_kernel<<<gw, 256>>>(Wq, wq, Wk, wk, Wv, wv, Wo, wo);
    pack16x2_kernel<<<ga, 256>>>(x, pa, mem, pm);

    // Stage 1 QKV (rope + vT fused)
    gemm16_multi<0><<<g3, 256, SMEM_TC>>>(pa, wq, wk, wv, bq, bk, bv, q, k1, vt1, R);

    // flash1 co-scheduled with stage-2 KV GEMM
    fat_kernel<<<gfat, 256, SMEM_FAT>>>(q, k1, vt1, y, pm, wk, wv, bk, bv, k2, vt2);

    // flash2 with fused q projection (no standalone q2 GEMM, no q roundtrip)
    flash2q_kernel<<<gf, 256, SMEM_FL>>>(y, wq, bq, k2, vt2, y);

    // Output projection (fp32 out)
    gemm16_multi<3><<<g1, 256, SMEM_TC>>>(y, wo, wo, wo, bo, bo, bo, out, out, out, R);
}